// round 1
// baseline (speedup 1.0000x reference)
#include <cuda_runtime.h>
#include <math.h>

// Problem constants (fixed by setup_inputs)
#define Bb    8
#define Hh    8
#define DHd   64
#define Ff    16
#define NSP   196          // spatial tokens per frame
#define NTOK  3137         // 1 + Ff*NSP
#define DIM   512
#define QKVD  1536
#define MROWS 25096        // Bb * NTOK

// Scratch (alloc-free rule: __device__ globals)
__device__ float g_qkv [38547456];  // MROWS * QKVD
__device__ float g_attn[12849152];  // MROWS * DIM

// ---------------------------------------------------------------------------
// SIMT GEMM: C[M,Nc] = A[M,K] @ B[K,Nc] (+ bias). 128x128x16 tile, 8x8/thread.
// useGA: A = g_attn (ignore Aext). useGC: C = g_qkv (ignore Cext).
// ---------------------------------------------------------------------------
__global__ __launch_bounds__(256)
void gemm_kernel(const float* __restrict__ Aext, const float* __restrict__ Bmat,
                 const float* __restrict__ bias, float* __restrict__ Cext,
                 int M, int Nc, int K, int useGA, int useGC)
{
    const float* A = useGA ? (const float*)g_attn : Aext;
    float*       C = useGC ? (float*)g_qkv       : Cext;

    __shared__ float As[16][128];
    __shared__ float Bs[16][128];

    const int tid = threadIdx.x;
    const int rowBase = blockIdx.y * 128;
    const int colBase = blockIdx.x * 128;
    const int tx = tid & 15;       // 0..15 -> col group
    const int ty = tid >> 4;       // 0..15 -> row group

    float acc[8][8];
    #pragma unroll
    for (int i = 0; i < 8; i++)
        #pragma unroll
        for (int j = 0; j < 8; j++) acc[i][j] = 0.f;

    for (int k0 = 0; k0 < K; k0 += 16) {
        // Load A tile 128x16 (transposed into As[k][m]); guard ragged M
        #pragma unroll
        for (int l = 0; l < 2; l++) {
            int v  = tid + l * 256;          // 0..511 float4 slots
            int r  = v >> 2;                 // row 0..127
            int c4 = (v & 3) << 2;           // k-col 0,4,8,12
            int gr = rowBase + r;
            float4 val = make_float4(0.f, 0.f, 0.f, 0.f);
            if (gr < M)
                val = *reinterpret_cast<const float4*>(&A[(size_t)gr * K + k0 + c4]);
            As[c4 + 0][r] = val.x;
            As[c4 + 1][r] = val.y;
            As[c4 + 2][r] = val.z;
            As[c4 + 3][r] = val.w;
        }
        // Load B tile 16x128 (K,Nc exact multiples — no guard)
        #pragma unroll
        for (int l = 0; l < 2; l++) {
            int v = tid + l * 256;
            int r = v >> 5;                  // k-row 0..15
            int c = (v & 31) << 2;           // col 0..124
            float4 val = *reinterpret_cast<const float4*>(
                &Bmat[(size_t)(k0 + r) * Nc + colBase + c]);
            *reinterpret_cast<float4*>(&Bs[r][c]) = val;
        }
        __syncthreads();

        #pragma unroll
        for (int k = 0; k < 16; k++) {
            float a[8], b[8];
            #pragma unroll
            for (int i = 0; i < 8; i++) a[i] = As[k][ty * 8 + i];
            #pragma unroll
            for (int j = 0; j < 8; j++) b[j] = Bs[k][tx * 8 + j];
            #pragma unroll
            for (int i = 0; i < 8; i++)
                #pragma unroll
                for (int j = 0; j < 8; j++)
                    acc[i][j] += a[i] * b[j];
        }
        __syncthreads();
    }

    const int gc = colBase + tx * 8;
    float bb[8];
    #pragma unroll
    for (int j = 0; j < 8; j++) bb[j] = bias ? bias[gc + j] : 0.f;

    #pragma unroll
    for (int i = 0; i < 8; i++) {
        int gr = rowBase + ty * 8 + i;
        if (gr >= M) continue;
        float4 o0, o1;
        o0.x = acc[i][0] + bb[0]; o0.y = acc[i][1] + bb[1];
        o0.z = acc[i][2] + bb[2]; o0.w = acc[i][3] + bb[3];
        o1.x = acc[i][4] + bb[4]; o1.y = acc[i][5] + bb[5];
        o1.z = acc[i][6] + bb[6]; o1.w = acc[i][7] + bb[7];
        *reinterpret_cast<float4*>(&C[(size_t)gr * Nc + gc])     = o0;
        *reinterpret_cast<float4*>(&C[(size_t)gr * Nc + gc + 4]) = o1;
    }
}

// ---------------------------------------------------------------------------
// CLS attention: one block per (b,h). cls query attends over all NTOK keys.
// Writes attn output for token 0 into g_attn[(b,0,h*64+d)].
// ---------------------------------------------------------------------------
__global__ __launch_bounds__(256)
void cls_attn_kernel()
{
    __shared__ float sq[64];
    __shared__ float sc[NTOK];
    __shared__ float red[256];

    const int bh = blockIdx.x;
    const int b = bh / Hh, h = bh % Hh;
    const int tid = threadIdx.x;
    const float scale = 0.125f;   // DH^-0.5

    if (tid < 64)
        sq[tid] = g_qkv[(size_t)(b * NTOK) * QKVD + h * 64 + tid] * scale;
    __syncthreads();

    // scores + max
    float lmax = -1e30f;
    for (int t = tid; t < NTOK; t += 256) {
        const float4* kp = reinterpret_cast<const float4*>(
            &g_qkv[(size_t)(b * NTOK + t) * QKVD + DIM + h * 64]);
        float d0 = 0.f, d1 = 0.f, d2 = 0.f, d3 = 0.f;
        #pragma unroll
        for (int i = 0; i < 16; i++) {
            float4 kv = kp[i];
            d0 += sq[4*i + 0] * kv.x;
            d1 += sq[4*i + 1] * kv.y;
            d2 += sq[4*i + 2] * kv.z;
            d3 += sq[4*i + 3] * kv.w;
        }
        float dot = (d0 + d1) + (d2 + d3);
        sc[t] = dot;
        lmax = fmaxf(lmax, dot);
    }
    red[tid] = lmax; __syncthreads();
    for (int s = 128; s > 0; s >>= 1) {
        if (tid < s) red[tid] = fmaxf(red[tid], red[tid + s]);
        __syncthreads();
    }
    const float m = red[0];
    __syncthreads();

    // exp + sum
    float lsum = 0.f;
    for (int t = tid; t < NTOK; t += 256) {
        float e = expf(sc[t] - m);
        sc[t] = e;
        lsum += e;
    }
    red[tid] = lsum; __syncthreads();
    for (int s = 128; s > 0; s >>= 1) {
        if (tid < s) red[tid] += red[tid + s];
        __syncthreads();
    }
    const float inv = 1.0f / red[0];
    __syncthreads();

    // weighted sum of V: thread (chunk, d); 4 chunks over tokens, 64 dims
    const int d = tid & 63, chunk = tid >> 6;
    float acc = 0.f;
    for (int t = chunk; t < NTOK; t += 4)
        acc += sc[t] * g_qkv[(size_t)(b * NTOK + t) * QKVD + 2 * DIM + h * 64 + d];
    red[tid] = acc; __syncthreads();
    if (chunk == 0) {
        float tot = acc + red[tid + 64] + red[tid + 128] + red[tid + 192];
        g_attn[(size_t)(b * NTOK) * DIM + h * 64 + d] = tot * inv;
    }
}

// ---------------------------------------------------------------------------
// Time attention: one block per sequence s = (b*H + h)*NSP + j.
// 16 queries (frames) attend over 17 keys (cls + 16 frames) of dim 64.
// ---------------------------------------------------------------------------
__global__ __launch_bounds__(128)
void time_attn_kernel()
{
    __shared__ float Qs[16][65];
    __shared__ float Ks[17][65];
    __shared__ float Vs[17][65];

    const int s  = blockIdx.x;
    const int bh = s / NSP, j = s % NSP;
    const int b  = bh / Hh, h = bh % Hh;
    const int tid = threadIdx.x;
    const float scale = 0.125f;

    for (int idx = tid; idx < 16 * 64; idx += 128) {
        int i = idx >> 6, d = idx & 63;
        int t = 1 + i * NSP + j;
        Qs[i][d] = g_qkv[(size_t)(b * NTOK + t) * QKVD + h * 64 + d] * scale;
    }
    for (int idx = tid; idx < 17 * 64; idx += 128) {
        int key = idx >> 6, d = idx & 63;
        int t = (key == 0) ? 0 : 1 + (key - 1) * NSP + j;
        size_t base = (size_t)(b * NTOK + t) * QKVD + h * 64 + d;
        Ks[key][d] = g_qkv[base + DIM];
        Vs[key][d] = g_qkv[base + 2 * DIM];
    }
    __syncthreads();

    const int w = tid >> 5, lane = tid & 31;
    for (int qi = w; qi < 16; qi += 4) {
        float scv = -1e30f;
        if (lane < 17) {
            float a = 0.f;
            #pragma unroll
            for (int d = 0; d < 64; d++) a += Qs[qi][d] * Ks[lane][d];
            scv = a;
        }
        float m = scv;
        #pragma unroll
        for (int o = 16; o > 0; o >>= 1)
            m = fmaxf(m, __shfl_xor_sync(0xffffffffu, m, o));
        float e = (lane < 17) ? expf(scv - m) : 0.f;
        float ssum = e;
        #pragma unroll
        for (int o = 16; o > 0; o >>= 1)
            ssum += __shfl_xor_sync(0xffffffffu, ssum, o);
        float p = e / ssum;

        float a0 = 0.f, a1 = 0.f;
        #pragma unroll
        for (int kk = 0; kk < 17; kk++) {
            float pj = __shfl_sync(0xffffffffu, p, kk);
            a0 += pj * Vs[kk][lane];
            a1 += pj * Vs[kk][lane + 32];
        }
        int t = 1 + qi * NSP + j;
        size_t ob = (size_t)(b * NTOK + t) * DIM + h * 64;
        g_attn[ob + lane]      = a0;
        g_attn[ob + lane + 32] = a1;
    }
}

// ---------------------------------------------------------------------------
// Launch
// ---------------------------------------------------------------------------
extern "C" void kernel_launch(void* const* d_in, const int* in_sizes, int n_in,
                              void* d_out, int out_size)
{
    const float* x    = (const float*)d_in[0];   // [B, N, 512]
    const float* Wqkv = (const float*)d_in[1];   // [512, 1536]
    const float* Wout = (const float*)d_in[2];   // [512, 512]
    const float* bout = (const float*)d_in[3];   // [512]
    float* out = (float*)d_out;                  // [B, N, 512]

    // 1) qkv = x @ Wqkv  -> g_qkv
    {
        dim3 grid(QKVD / 128, (MROWS + 127) / 128);
        gemm_kernel<<<grid, 256>>>(x, Wqkv, nullptr, nullptr,
                                   MROWS, QKVD, DIM, 0, 1);
    }
    // 2) attention -> g_attn
    cls_attn_kernel<<<Bb * Hh, 256>>>();
    time_attn_kernel<<<Bb * Hh * NSP, 128>>>();
    // 3) out = g_attn @ Wout + bout
    {
        dim3 grid(DIM / 128, (MROWS + 127) / 128);
        gemm_kernel<<<grid, 256>>>(nullptr, Wout, bout, out,
                                   MROWS, DIM, DIM, 1, 0);
    }
}

// round 7
// speedup vs baseline: 1.2375x; 1.2375x over previous
#include <cuda_runtime.h>
#include <cuda_bf16.h>
#include <cstdint>
#include <math.h>

// Problem constants (fixed by setup_inputs)
#define Bb    8
#define Hh    8
#define NSP   196
#define NTOK  3137
#define DIM   512
#define QKVD  1536
#define MROWS 25096        // Bb * NTOK

// -------------------- scratch (__device__ globals, alloc-free) --------------
// Exactly the round-1 (passing) scratch set.
__device__ float g_qkv [38547456];  // MROWS * QKVD
__device__ float g_attn[12849152];  // MROWS * DIM

// -------------------- PTX helpers (sm_80-baseline only) ---------------------
__device__ __forceinline__ uint32_t smem_u32(const void* p) {
    uint32_t a;
    asm("{ .reg .u64 t; cvta.to.shared.u64 t, %1; cvt.u32.u64 %0, t; }"
        : "=r"(a) : "l"(p));
    return a;
}
__device__ __forceinline__ uint32_t lds32(uint32_t a) {
    uint32_t v;
    asm volatile("ld.shared.b32 %0, [%1];" : "=r"(v) : "r"(a));
    return v;
}
__device__ __forceinline__ void sts32(uint32_t a, uint32_t v) {
    asm volatile("st.shared.b32 [%0], %1;" :: "r"(a), "r"(v) : "memory");
}
__device__ __forceinline__ void mma_bf16(float* c, const uint32_t* a,
                                         uint32_t b0, uint32_t b1) {
    asm volatile(
        "mma.sync.aligned.m16n8k16.row.col.f32.bf16.bf16.f32 "
        "{%0,%1,%2,%3}, {%4,%5,%6,%7}, {%8,%9}, {%0,%1,%2,%3};"
        : "+f"(c[0]), "+f"(c[1]), "+f"(c[2]), "+f"(c[3])
        : "r"(a[0]), "r"(a[1]), "r"(a[2]), "r"(a[3]), "r"(b0), "r"(b1));
}
// split (x,y) fp32 pair into packed bf16 hi-pair and lo-pair
__device__ __forceinline__ void split2(float x, float y,
                                       uint32_t& hi, uint32_t& lo) {
    __nv_bfloat16 hx = __float2bfloat16(x);
    __nv_bfloat16 hy = __float2bfloat16(y);
    __nv_bfloat16 lx = __float2bfloat16(x - __bfloat162float(hx));
    __nv_bfloat16 ly = __float2bfloat16(y - __bfloat162float(hy));
    __nv_bfloat162 h2 = __halves2bfloat162(hx, hy);
    __nv_bfloat162 l2 = __halves2bfloat162(lx, ly);
    hi = *reinterpret_cast<uint32_t*>(&h2);
    lo = *reinterpret_cast<uint32_t*>(&l2);
}

// -------------------- mma.sync GEMM ----------------------------------------
// C[M,Nc] = A[M,512] @ W[512,Nc] (+bias). fp32 inputs, in-register hi/lo
// bf16 split, 3-term mma (hh + hl + lh), fp32 accum.
// Block tile 128x128, k-step 16, single smem stage + register double buffer.
// mode 0: A = Aext (x),   C = g_qkv
// mode 1: A = g_attn,     C = Cext
#define ROWB   48                 // 32B data + 16B pad (conflict-free lds)
#define MATB   (128 * ROWB)       // 6144 bytes per matrix tile
// layout: Ahi @0, Alo @MATB, Bhi @2*MATB, Blo @3*MATB  (24576 B total)

__global__ __launch_bounds__(256)
void gemm_mma_kernel(const float* __restrict__ Aext, const float* __restrict__ W,
                     const float* __restrict__ bias, float* __restrict__ Cext,
                     int M, int Nc, int mode)
{
    const float* A = (mode == 0) ? Aext : (const float*)g_attn;
    float*       C = (mode == 0) ? (float*)g_qkv : Cext;

    __shared__ uint32_t smem[4 * MATB / 4];   // 24576 bytes, 4B-aligned native
    uint32_t sb = smem_u32(smem);

    const int tid = threadIdx.x, wid = tid >> 5, lane = tid & 31;
    const int warpM = wid >> 2, warpN = wid & 3;
    const int gq = lane >> 2, tq = lane & 3;
    const int rowBase = blockIdx.y * 128, colBase = blockIdx.x * 128;

    // A staging: thread -> (row = tid>>1, half = tid&1), 8 floats
    const int arow = tid >> 1, ahalf = tid & 1;
    const int agr = min(rowBase + arow, M - 1);
    // B staging: thread -> (kpair = tid>>5, ngroup = tid&31), 4 n x 2 k floats
    const int bkp = tid >> 5, bng = tid & 31;

    float acc[4][4][4];
    #pragma unroll
    for (int i = 0; i < 4; i++)
        #pragma unroll
        for (int j = 0; j < 4; j++)
            #pragma unroll
            for (int e = 0; e < 4; e++) acc[i][j][e] = 0.f;

    // prologue: load k-slab 0 into registers
    float4 a0, a1, w0, w1;
    {
        const float* ap = A + (size_t)agr * DIM + ahalf * 8;
        a0 = *reinterpret_cast<const float4*>(ap);
        a1 = *reinterpret_cast<const float4*>(ap + 4);
        const float* wp = W + (size_t)(2 * bkp) * Nc + colBase + bng * 4;
        w0 = *reinterpret_cast<const float4*>(wp);
        w1 = *reinterpret_cast<const float4*>(wp + Nc);
    }

    const int nIter = DIM / 16;   // 32
    for (int it = 0; it < nIter; it++) {
        // ---- store staged registers to smem with hi/lo split ----
        {
            // A: row-major, element k at byte k*2
            uint32_t ab = sb + (uint32_t)arow * ROWB + (uint32_t)ahalf * 16;
            uint32_t hi, lo;
            split2(a0.x, a0.y, hi, lo); sts32(ab + 0,  hi); sts32(ab + 0  + MATB, lo);
            split2(a0.z, a0.w, hi, lo); sts32(ab + 4,  hi); sts32(ab + 4  + MATB, lo);
            split2(a1.x, a1.y, hi, lo); sts32(ab + 8,  hi); sts32(ab + 8  + MATB, lo);
            split2(a1.z, a1.w, hi, lo); sts32(ab + 12, hi); sts32(ab + 12 + MATB, lo);
            // B: transpose to [n-row, k-col]; pack k-pair (2bkp, 2bkp+1)
            const float* pw0 = &w0.x;
            const float* pw1 = &w1.x;
            #pragma unroll
            for (int e = 0; e < 4; e++) {
                int n = bng * 4 + e;
                uint32_t bbp = sb + 2 * MATB + (uint32_t)n * ROWB + (uint32_t)bkp * 4;
                split2(pw0[e], pw1[e], hi, lo);
                sts32(bbp, hi);
                sts32(bbp + MATB, lo);
            }
        }
        __syncthreads();

        // ---- prefetch next k-slab into registers (independent of smem) ----
        if (it + 1 < nIter) {
            int k0 = (it + 1) * 16;
            const float* ap = A + (size_t)agr * DIM + k0 + ahalf * 8;
            a0 = *reinterpret_cast<const float4*>(ap);
            a1 = *reinterpret_cast<const float4*>(ap + 4);
            const float* wp = W + (size_t)(k0 + 2 * bkp) * Nc + colBase + bng * 4;
            w0 = *reinterpret_cast<const float4*>(wp);
            w1 = *reinterpret_cast<const float4*>(wp + Nc);
        }

        // ---- fragments via plain lds (documented mma layouts) ----
        // A frags: a0=(row gq, k 2tq..), a1=(row gq+8, k 2tq..),
        //          a2=(row gq, k 8+2tq..), a3=(row gq+8, k 8+2tq..)
        uint32_t ah[4][4], al[4][4];
        uint32_t aoff = sb + (uint32_t)(warpM * 64 + gq) * ROWB + tq * 4;
        #pragma unroll
        for (int mf = 0; mf < 4; mf++) {
            uint32_t ba = aoff + (uint32_t)(mf * 16) * ROWB;
            ah[mf][0] = lds32(ba);
            ah[mf][1] = lds32(ba + 8 * ROWB);
            ah[mf][2] = lds32(ba + 16);
            ah[mf][3] = lds32(ba + 8 * ROWB + 16);
            al[mf][0] = lds32(ba + MATB);
            al[mf][1] = lds32(ba + MATB + 8 * ROWB);
            al[mf][2] = lds32(ba + MATB + 16);
            al[mf][3] = lds32(ba + MATB + 8 * ROWB + 16);
        }
        // B frags: b0=(n gq, k 2tq..), b1=(n gq, k 8+2tq..)
        uint32_t bh[4][2], bl[4][2];
        uint32_t boff = sb + 2 * MATB + (uint32_t)(warpN * 32 + gq) * ROWB + tq * 4;
        #pragma unroll
        for (int nf = 0; nf < 4; nf++) {
            uint32_t bbo = boff + (uint32_t)(nf * 8) * ROWB;
            bh[nf][0] = lds32(bbo);
            bh[nf][1] = lds32(bbo + 16);
            bl[nf][0] = lds32(bbo + MATB);
            bl[nf][1] = lds32(bbo + MATB + 16);
        }
        #pragma unroll
        for (int mf = 0; mf < 4; mf++)
            #pragma unroll
            for (int nf = 0; nf < 4; nf++) {
                mma_bf16(acc[mf][nf], ah[mf], bh[nf][0], bh[nf][1]);
                mma_bf16(acc[mf][nf], ah[mf], bl[nf][0], bl[nf][1]);
                mma_bf16(acc[mf][nf], al[mf], bh[nf][0], bh[nf][1]);
            }
        __syncthreads();   // all warps done reading before next store
    }

    // epilogue: direct float2 stores from documented C fragment layout
    // c0,c1 = (row gq, cols 2tq,2tq+1); c2,c3 = (row gq+8, same cols)
    #pragma unroll
    for (int nf = 0; nf < 4; nf++) {
        int col = colBase + warpN * 32 + nf * 8 + tq * 2;
        float2 bv = make_float2(0.f, 0.f);
        if (bias) bv = *reinterpret_cast<const float2*>(&bias[col]);
        #pragma unroll
        for (int mf = 0; mf < 4; mf++) {
            int r0 = rowBase + warpM * 64 + mf * 16 + gq;
            if (r0 < M) {
                float2 v = make_float2(acc[mf][nf][0] + bv.x,
                                       acc[mf][nf][1] + bv.y);
                *reinterpret_cast<float2*>(&C[(size_t)r0 * Nc + col]) = v;
            }
            int r1 = r0 + 8;
            if (r1 < M) {
                float2 v = make_float2(acc[mf][nf][2] + bv.x,
                                       acc[mf][nf][3] + bv.y);
                *reinterpret_cast<float2*>(&C[(size_t)r1 * Nc + col]) = v;
            }
        }
    }
}

// -------------------- CLS attention (verbatim round-1 passing code) ---------
__global__ __launch_bounds__(256)
void cls_attn_kernel()
{
    __shared__ float sq[64];
    __shared__ float sc[NTOK];
    __shared__ float red[256];

    const int bh = blockIdx.x;
    const int b = bh / Hh, h = bh % Hh;
    const int tid = threadIdx.x;
    const float scale = 0.125f;

    if (tid < 64)
        sq[tid] = g_qkv[(size_t)(b * NTOK) * QKVD + h * 64 + tid] * scale;
    __syncthreads();

    float lmax = -1e30f;
    for (int t = tid; t < NTOK; t += 256) {
        const float4* kp = reinterpret_cast<const float4*>(
            &g_qkv[(size_t)(b * NTOK + t) * QKVD + DIM + h * 64]);
        float d0 = 0.f, d1 = 0.f, d2 = 0.f, d3 = 0.f;
        #pragma unroll
        for (int i = 0; i < 16; i++) {
            float4 kv = kp[i];
            d0 += sq[4*i+0] * kv.x; d1 += sq[4*i+1] * kv.y;
            d2 += sq[4*i+2] * kv.z; d3 += sq[4*i+3] * kv.w;
        }
        float dot = (d0 + d1) + (d2 + d3);
        sc[t] = dot;
        lmax = fmaxf(lmax, dot);
    }
    red[tid] = lmax; __syncthreads();
    for (int s = 128; s > 0; s >>= 1) {
        if (tid < s) red[tid] = fmaxf(red[tid], red[tid + s]);
        __syncthreads();
    }
    const float m = red[0];
    __syncthreads();

    float lsum = 0.f;
    for (int t = tid; t < NTOK; t += 256) {
        float e = expf(sc[t] - m);
        sc[t] = e;
        lsum += e;
    }
    red[tid] = lsum; __syncthreads();
    for (int s = 128; s > 0; s >>= 1) {
        if (tid < s) red[tid] += red[tid + s];
        __syncthreads();
    }
    const float inv = 1.0f / red[0];
    __syncthreads();

    const int d = tid & 63, chunk = tid >> 6;
    float acc = 0.f;
    for (int t = chunk; t < NTOK; t += 4)
        acc += sc[t] * g_qkv[(size_t)(b * NTOK + t) * QKVD + 2 * DIM + h * 64 + d];
    red[tid] = acc; __syncthreads();
    if (chunk == 0) {
        float tot = acc + red[tid + 64] + red[tid + 128] + red[tid + 192];
        g_attn[(size_t)(b * NTOK) * DIM + h * 64 + d] = tot * inv;
    }
}

// -------------------- time attention (verbatim round-1 passing code) --------
__global__ __launch_bounds__(128)
void time_attn_kernel()
{
    __shared__ float Qs[16][65];
    __shared__ float Ks[17][65];
    __shared__ float Vs[17][65];

    const int s  = blockIdx.x;
    const int bh = s / NSP, j = s % NSP;
    const int b  = bh / Hh, h = bh % Hh;
    const int tid = threadIdx.x;
    const float scale = 0.125f;

    for (int idx = tid; idx < 16 * 64; idx += 128) {
        int i = idx >> 6, d = idx & 63;
        int t = 1 + i * NSP + j;
        Qs[i][d] = g_qkv[(size_t)(b * NTOK + t) * QKVD + h * 64 + d] * scale;
    }
    for (int idx = tid; idx < 17 * 64; idx += 128) {
        int key = idx >> 6, d = idx & 63;
        int t = (key == 0) ? 0 : 1 + (key - 1) * NSP + j;
        size_t base = (size_t)(b * NTOK + t) * QKVD + h * 64 + d;
        Ks[key][d] = g_qkv[base + DIM];
        Vs[key][d] = g_qkv[base + 2 * DIM];
    }
    __syncthreads();

    const int w = tid >> 5, lane = tid & 31;
    for (int qi = w; qi < 16; qi += 4) {
        float scv = -1e30f;
        if (lane < 17) {
            float a = 0.f;
            #pragma unroll
            for (int d = 0; d < 64; d++) a += Qs[qi][d] * Ks[lane][d];
            scv = a;
        }
        float m = scv;
        #pragma unroll
        for (int o = 16; o > 0; o >>= 1)
            m = fmaxf(m, __shfl_xor_sync(0xffffffffu, m, o));
        float e = (lane < 17) ? expf(scv - m) : 0.f;
        float ssum = e;
        #pragma unroll
        for (int o = 16; o > 0; o >>= 1)
            ssum += __shfl_xor_sync(0xffffffffu, ssum, o);
        float p = e / ssum;

        float a0 = 0.f, a1 = 0.f;
        #pragma unroll
        for (int kk = 0; kk < 17; kk++) {
            float pj = __shfl_sync(0xffffffffu, p, kk);
            a0 += pj * Vs[kk][lane];
            a1 += pj * Vs[kk][lane + 32];
        }
        int t = 1 + qi * NSP + j;
        size_t ob = (size_t)(b * NTOK + t) * DIM + h * 64;
        g_attn[ob + lane]      = a0;
        g_attn[ob + lane + 32] = a1;
    }
}

// -------------------- launch -----------------------------------------------
extern "C" void kernel_launch(void* const* d_in, const int* in_sizes, int n_in,
                              void* d_out, int out_size)
{
    const float* x    = (const float*)d_in[0];   // [B, N, 512]
    const float* Wqkv = (const float*)d_in[1];   // [512, 1536]
    const float* Wout = (const float*)d_in[2];   // [512, 512]
    const float* bout = (const float*)d_in[3];   // [512]
    float* out = (float*)d_out;

    // 1) qkv = x @ Wqkv -> g_qkv
    {
        dim3 grid(QKVD / 128, (MROWS + 127) / 128);
        gemm_mma_kernel<<<grid, 256>>>(x, Wqkv, nullptr, nullptr,
                                       MROWS, QKVD, 0);
    }
    // 2) attention -> g_attn
    cls_attn_kernel<<<Bb * Hh, 256>>>();
    time_attn_kernel<<<Bb * Hh * NSP, 128>>>();
    // 3) out = g_attn @ Wout + bias
    {
        dim3 grid(DIM / 128, (MROWS + 127) / 128);
        gemm_mma_kernel<<<grid, 256>>>(nullptr, Wout, bout, out,
                                       MROWS, DIM, 1);
    }
}

// round 8
// speedup vs baseline: 1.4271x; 1.1532x over previous
#include <cuda_runtime.h>
#include <cuda_bf16.h>
#include <cstdint>
#include <math.h>

// Problem constants (fixed by setup_inputs)
#define Bb    8
#define Hh    8
#define NSP   196
#define NTOK  3137
#define DIM   512
#define QKVD  1536
#define MROWS 25096        // Bb * NTOK

// -------------------- scratch (__device__ globals, alloc-free) --------------
__device__ float g_qkv [38547456];  // MROWS * QKVD
__device__ float g_attn[12849152];  // MROWS * DIM
__device__ float g_clsm[512];       // cls partial max   (bh*8+c)
__device__ float g_clss[512];       // cls partial sum
__device__ float g_clso[32768];     // cls partial out   (bh*8+c, d)

// -------------------- PTX helpers (sm_80-baseline only) ---------------------
__device__ __forceinline__ uint32_t smem_u32(const void* p) {
    uint32_t a;
    asm("{ .reg .u64 t; cvta.to.shared.u64 t, %1; cvt.u32.u64 %0, t; }"
        : "=r"(a) : "l"(p));
    return a;
}
__device__ __forceinline__ uint32_t lds32(uint32_t a) {
    uint32_t v;
    asm volatile("ld.shared.b32 %0, [%1];" : "=r"(v) : "r"(a));
    return v;
}
__device__ __forceinline__ void sts32(uint32_t a, uint32_t v) {
    asm volatile("st.shared.b32 [%0], %1;" :: "r"(a), "r"(v) : "memory");
}
__device__ __forceinline__ void mma_bf16(float* c, const uint32_t* a,
                                         uint32_t b0, uint32_t b1) {
    asm volatile(
        "mma.sync.aligned.m16n8k16.row.col.f32.bf16.bf16.f32 "
        "{%0,%1,%2,%3}, {%4,%5,%6,%7}, {%8,%9}, {%0,%1,%2,%3};"
        : "+f"(c[0]), "+f"(c[1]), "+f"(c[2]), "+f"(c[3])
        : "r"(a[0]), "r"(a[1]), "r"(a[2]), "r"(a[3]), "r"(b0), "r"(b1));
}
__device__ __forceinline__ void split2(float x, float y,
                                       uint32_t& hi, uint32_t& lo) {
    __nv_bfloat16 hx = __float2bfloat16(x);
    __nv_bfloat16 hy = __float2bfloat16(y);
    __nv_bfloat16 lx = __float2bfloat16(x - __bfloat162float(hx));
    __nv_bfloat16 ly = __float2bfloat16(y - __bfloat162float(hy));
    __nv_bfloat162 h2 = __halves2bfloat162(hx, hy);
    __nv_bfloat162 l2 = __halves2bfloat162(lx, ly);
    hi = *reinterpret_cast<uint32_t*>(&h2);
    lo = *reinterpret_cast<uint32_t*>(&l2);
}

// -------------------- mma.sync GEMM ----------------------------------------
// C[M,Nc] = A[M,512] @ W[512,Nc] (+bias). fp32 inputs, in-register hi/lo
// bf16 split, 3-term mma, fp32 accum. 128x128 tile, k-step 16,
// DOUBLE-buffered smem (1 sync/iter), register prefetch.
// smem stage layout (bytes):
//   Ahi @ 0      (128 rows x 48B)   = 6144
//   Alo @ 6144                      = 6144
//   Bhi @ 12288  (8 kpairs x 544B)  = 4352
//   Blo @ 16640                     = 4352
#define AROWB  48
#define A_MATB 6144
#define B_PITCH 544
#define B_MATB 4352
#define B_OFF  12288
#define STAGEB 20992            // 164 * 128

__global__ __launch_bounds__(256)
void gemm_mma_kernel(const float* __restrict__ Aext, const float* __restrict__ W,
                     const float* __restrict__ bias, float* __restrict__ Cext,
                     int M, int Nc, int mode)
{
    const float* A = (mode == 0) ? Aext : (const float*)g_attn;
    float*       C = (mode == 0) ? (float*)g_qkv : Cext;

    __shared__ uint32_t smem[2 * STAGEB / 4];   // 41984 bytes static
    uint32_t sb = smem_u32(smem);

    const int tid = threadIdx.x, wid = tid >> 5, lane = tid & 31;
    const int warpM = wid >> 2, warpN = wid & 3;
    const int gq = lane >> 2, tq = lane & 3;
    const int rowBase = blockIdx.y * 128, colBase = blockIdx.x * 128;

    // A staging: thread -> (row = tid>>1, half = tid&1): 8 floats (k half)
    const int arow = tid >> 1, ahalf = tid & 1;
    const int agr = min(rowBase + arow, M - 1);
    // B staging: thread -> (kpair = tid>>5, 4 n at lane*4): 2 k x 4 n floats
    const int bkp = tid >> 5;

    float acc[4][4][4];
    #pragma unroll
    for (int i = 0; i < 4; i++)
        #pragma unroll
        for (int j = 0; j < 4; j++)
            #pragma unroll
            for (int e = 0; e < 4; e++) acc[i][j][e] = 0.f;

    float4 a0, a1, w0, w1;
    // load slab 0
    {
        const float* ap = A + (size_t)agr * DIM + ahalf * 8;
        a0 = *reinterpret_cast<const float4*>(ap);
        a1 = *reinterpret_cast<const float4*>(ap + 4);
        const float* wp = W + (size_t)(2 * bkp) * Nc + colBase + lane * 4;
        w0 = *reinterpret_cast<const float4*>(wp);
        w1 = *reinterpret_cast<const float4*>(wp + Nc);
    }
    // store slab 0 -> buffer 0
    {
        uint32_t st = sb;
        uint32_t ab = st + (uint32_t)arow * AROWB + (uint32_t)ahalf * 16;
        uint32_t hi, lo;
        split2(a0.x, a0.y, hi, lo); sts32(ab + 0,  hi); sts32(ab + 0  + A_MATB, lo);
        split2(a0.z, a0.w, hi, lo); sts32(ab + 4,  hi); sts32(ab + 4  + A_MATB, lo);
        split2(a1.x, a1.y, hi, lo); sts32(ab + 8,  hi); sts32(ab + 8  + A_MATB, lo);
        split2(a1.z, a1.w, hi, lo); sts32(ab + 12, hi); sts32(ab + 12 + A_MATB, lo);
        const float* pw0 = &w0.x;
        const float* pw1 = &w1.x;
        #pragma unroll
        for (int e = 0; e < 4; e++) {
            uint32_t bp = st + B_OFF + (uint32_t)bkp * B_PITCH
                        + (uint32_t)(lane * 4 + e) * 4;
            split2(pw0[e], pw1[e], hi, lo);
            sts32(bp, hi);
            sts32(bp + B_MATB, lo);
        }
    }

    const int nIter = DIM / 16;   // 32
    for (int it = 0; it < nIter; it++) {
        // prefetch next slab into registers
        if (it + 1 < nIter) {
            int k0 = (it + 1) * 16;
            const float* ap = A + (size_t)agr * DIM + k0 + ahalf * 8;
            a0 = *reinterpret_cast<const float4*>(ap);
            a1 = *reinterpret_cast<const float4*>(ap + 4);
            const float* wp = W + (size_t)(k0 + 2 * bkp) * Nc + colBase + lane * 4;
            w0 = *reinterpret_cast<const float4*>(wp);
            w1 = *reinterpret_cast<const float4*>(wp + Nc);
        }
        __syncthreads();          // buffer (it&1) fully written; prev reads done

        uint32_t stg = sb + (uint32_t)(it & 1) * STAGEB;
        // ---- load fragments ----
        uint32_t ah[4][4], al[4][4];
        uint32_t aoff = stg + (uint32_t)(warpM * 64 + gq) * AROWB + tq * 4;
        #pragma unroll
        for (int mf = 0; mf < 4; mf++) {
            uint32_t ba = aoff + (uint32_t)(mf * 16) * AROWB;
            ah[mf][0] = lds32(ba);
            ah[mf][1] = lds32(ba + 8 * AROWB);
            ah[mf][2] = lds32(ba + 16);
            ah[mf][3] = lds32(ba + 8 * AROWB + 16);
            al[mf][0] = lds32(ba + A_MATB);
            al[mf][1] = lds32(ba + A_MATB + 8 * AROWB);
            al[mf][2] = lds32(ba + A_MATB + 16);
            al[mf][3] = lds32(ba + A_MATB + 8 * AROWB + 16);
        }
        uint32_t bh[4][2], bl[4][2];
        {
            uint32_t b0base = stg + B_OFF + (uint32_t)tq * B_PITCH
                            + (uint32_t)(warpN * 32 + gq) * 4;
            #pragma unroll
            for (int nf = 0; nf < 4; nf++) {
                uint32_t bbo = b0base + (uint32_t)(nf * 8) * 4;
                bh[nf][0] = lds32(bbo);
                bh[nf][1] = lds32(bbo + 4 * B_PITCH);
                bl[nf][0] = lds32(bbo + B_MATB);
                bl[nf][1] = lds32(bbo + B_MATB + 4 * B_PITCH);
            }
        }
        // ---- store next slab to the OTHER buffer (overlaps with MMA) ----
        if (it + 1 < nIter) {
            uint32_t st = sb + (uint32_t)((it + 1) & 1) * STAGEB;
            uint32_t ab = st + (uint32_t)arow * AROWB + (uint32_t)ahalf * 16;
            uint32_t hi, lo;
            split2(a0.x, a0.y, hi, lo); sts32(ab + 0,  hi); sts32(ab + 0  + A_MATB, lo);
            split2(a0.z, a0.w, hi, lo); sts32(ab + 4,  hi); sts32(ab + 4  + A_MATB, lo);
            split2(a1.x, a1.y, hi, lo); sts32(ab + 8,  hi); sts32(ab + 8  + A_MATB, lo);
            split2(a1.z, a1.w, hi, lo); sts32(ab + 12, hi); sts32(ab + 12 + A_MATB, lo);
            const float* pw0 = &w0.x;
            const float* pw1 = &w1.x;
            #pragma unroll
            for (int e = 0; e < 4; e++) {
                uint32_t bp = st + B_OFF + (uint32_t)bkp * B_PITCH
                            + (uint32_t)(lane * 4 + e) * 4;
                split2(pw0[e], pw1[e], hi, lo);
                sts32(bp, hi);
                sts32(bp + B_MATB, lo);
            }
        }
        // ---- MMAs ----
        #pragma unroll
        for (int mf = 0; mf < 4; mf++)
            #pragma unroll
            for (int nf = 0; nf < 4; nf++) {
                mma_bf16(acc[mf][nf], ah[mf], bh[nf][0], bh[nf][1]);
                mma_bf16(acc[mf][nf], ah[mf], bl[nf][0], bl[nf][1]);
                mma_bf16(acc[mf][nf], al[mf], bh[nf][0], bh[nf][1]);
            }
    }

    // epilogue: direct float2 stores (documented C fragment layout)
    #pragma unroll
    for (int nf = 0; nf < 4; nf++) {
        int col = colBase + warpN * 32 + nf * 8 + tq * 2;
        float2 bv = make_float2(0.f, 0.f);
        if (bias) bv = *reinterpret_cast<const float2*>(&bias[col]);
        #pragma unroll
        for (int mf = 0; mf < 4; mf++) {
            int r0 = rowBase + warpM * 64 + mf * 16 + gq;
            if (r0 < M) {
                float2 v = make_float2(acc[mf][nf][0] + bv.x,
                                       acc[mf][nf][1] + bv.y);
                *reinterpret_cast<float2*>(&C[(size_t)r0 * Nc + col]) = v;
            }
            int r1 = r0 + 8;
            if (r1 < M) {
                float2 v = make_float2(acc[mf][nf][2] + bv.x,
                                       acc[mf][nf][3] + bv.y);
                *reinterpret_cast<float2*>(&C[(size_t)r1 * Nc + col]) = v;
            }
        }
    }
}

// -------------------- CLS attention: chunked partials + merge ---------------
#define CLS_CH 393     // ceil(3137/8)

__global__ __launch_bounds__(256)
void cls_partial_kernel()
{
    __shared__ float sq[64];
    __shared__ float sc[CLS_CH];
    __shared__ float red[256];

    const int bx = blockIdx.x;           // bh*8 + c
    const int bh = bx >> 3, c = bx & 7;
    const int b = bh / Hh, h = bh % Hh;
    const int tid = threadIdx.x;
    const float scale = 0.125f;
    const int t0 = c * CLS_CH, t1 = min(NTOK, t0 + CLS_CH);

    if (tid < 64)
        sq[tid] = g_qkv[(size_t)(b * NTOK) * QKVD + h * 64 + tid] * scale;
    __syncthreads();

    float lmax = -1e30f;
    for (int t = t0 + tid; t < t1; t += 256) {
        const float4* kp = reinterpret_cast<const float4*>(
            &g_qkv[(size_t)(b * NTOK + t) * QKVD + DIM + h * 64]);
        float d0 = 0.f, d1 = 0.f, d2 = 0.f, d3 = 0.f;
        #pragma unroll
        for (int i = 0; i < 16; i++) {
            float4 kv = kp[i];
            d0 += sq[4*i+0] * kv.x; d1 += sq[4*i+1] * kv.y;
            d2 += sq[4*i+2] * kv.z; d3 += sq[4*i+3] * kv.w;
        }
        float dot = (d0 + d1) + (d2 + d3);
        sc[t - t0] = dot;
        lmax = fmaxf(lmax, dot);
    }
    red[tid] = lmax; __syncthreads();
    for (int s = 128; s > 0; s >>= 1) {
        if (tid < s) red[tid] = fmaxf(red[tid], red[tid + s]);
        __syncthreads();
    }
    const float m = red[0];
    __syncthreads();

    float lsum = 0.f;
    for (int t = t0 + tid; t < t1; t += 256) {
        float e = expf(sc[t - t0] - m);
        sc[t - t0] = e;
        lsum += e;
    }
    red[tid] = lsum; __syncthreads();
    for (int s = 128; s > 0; s >>= 1) {
        if (tid < s) red[tid] += red[tid + s];
        __syncthreads();
    }
    const float ssum = red[0];
    __syncthreads();

    const int d = tid & 63, chunk = tid >> 6;
    float acc = 0.f;
    for (int t = t0 + chunk; t < t1; t += 4)
        acc += sc[t - t0] * g_qkv[(size_t)(b * NTOK + t) * QKVD + 2 * DIM + h * 64 + d];
    red[tid] = acc; __syncthreads();
    if (chunk == 0) {
        float tot = acc + red[tid + 64] + red[tid + 128] + red[tid + 192];
        g_clso[bx * 64 + d] = tot;
        if (d == 0) { g_clsm[bx] = m; g_clss[bx] = ssum; }
    }
}

__global__ __launch_bounds__(64)
void cls_merge_kernel()
{
    const int bh = blockIdx.x;
    const int b = bh / Hh, h = bh % Hh;
    const int d = threadIdx.x;

    float M = -1e30f;
    #pragma unroll
    for (int c = 0; c < 8; c++) M = fmaxf(M, g_clsm[bh * 8 + c]);
    float S = 0.f, O = 0.f;
    #pragma unroll
    for (int c = 0; c < 8; c++) {
        float w = expf(g_clsm[bh * 8 + c] - M);
        S += g_clss[bh * 8 + c] * w;
        O += g_clso[(bh * 8 + c) * 64 + d] * w;
    }
    g_attn[(size_t)(b * NTOK) * DIM + h * 64 + d] = O / S;
}

// -------------------- time attention (verbatim passing code) ---------------
__global__ __launch_bounds__(128)
void time_attn_kernel()
{
    __shared__ float Qs[16][65];
    __shared__ float Ks[17][65];
    __shared__ float Vs[17][65];

    const int s  = blockIdx.x;
    const int bh = s / NSP, j = s % NSP;
    const int b  = bh / Hh, h = bh % Hh;
    const int tid = threadIdx.x;
    const float scale = 0.125f;

    for (int idx = tid; idx < 16 * 64; idx += 128) {
        int i = idx >> 6, d = idx & 63;
        int t = 1 + i * NSP + j;
        Qs[i][d] = g_qkv[(size_t)(b * NTOK + t) * QKVD + h * 64 + d] * scale;
    }
    for (int idx = tid; idx < 17 * 64; idx += 128) {
        int key = idx >> 6, d = idx & 63;
        int t = (key == 0) ? 0 : 1 + (key - 1) * NSP + j;
        size_t base = (size_t)(b * NTOK + t) * QKVD + h * 64 + d;
        Ks[key][d] = g_qkv[base + DIM];
        Vs[key][d] = g_qkv[base + 2 * DIM];
    }
    __syncthreads();

    const int w = tid >> 5, lane = tid & 31;
    for (int qi = w; qi < 16; qi += 4) {
        float scv = -1e30f;
        if (lane < 17) {
            float a = 0.f;
            #pragma unroll
            for (int d = 0; d < 64; d++) a += Qs[qi][d] * Ks[lane][d];
            scv = a;
        }
        float m = scv;
        #pragma unroll
        for (int o = 16; o > 0; o >>= 1)
            m = fmaxf(m, __shfl_xor_sync(0xffffffffu, m, o));
        float e = (lane < 17) ? expf(scv - m) : 0.f;
        float ssum = e;
        #pragma unroll
        for (int o = 16; o > 0; o >>= 1)
            ssum += __shfl_xor_sync(0xffffffffu, ssum, o);
        float p = e / ssum;

        float a0 = 0.f, a1 = 0.f;
        #pragma unroll
        for (int kk = 0; kk < 17; kk++) {
            float pj = __shfl_sync(0xffffffffu, p, kk);
            a0 += pj * Vs[kk][lane];
            a1 += pj * Vs[kk][lane + 32];
        }
        int t = 1 + qi * NSP + j;
        size_t ob = (size_t)(b * NTOK + t) * DIM + h * 64;
        g_attn[ob + lane]      = a0;
        g_attn[ob + lane + 32] = a1;
    }
}

// -------------------- launch -----------------------------------------------
extern "C" void kernel_launch(void* const* d_in, const int* in_sizes, int n_in,
                              void* d_out, int out_size)
{
    const float* x    = (const float*)d_in[0];   // [B, N, 512]
    const float* Wqkv = (const float*)d_in[1];   // [512, 1536]
    const float* Wout = (const float*)d_in[2];   // [512, 512]
    const float* bout = (const float*)d_in[3];   // [512]
    float* out = (float*)d_out;

    // 1) qkv = x @ Wqkv -> g_qkv
    {
        dim3 grid(QKVD / 128, (MROWS + 127) / 128);
        gemm_mma_kernel<<<grid, 256>>>(x, Wqkv, nullptr, nullptr,
                                       MROWS, QKVD, 0);
    }
    // 2) attention -> g_attn
    cls_partial_kernel<<<512, 256>>>();
    cls_merge_kernel<<<Bb * Hh, 64>>>();
    time_attn_kernel<<<Bb * Hh * NSP, 128>>>();
    // 3) out = g_attn @ Wout + bias
    {
        dim3 grid(DIM / 128, (MROWS + 127) / 128);
        gemm_mma_kernel<<<grid, 256>>>(nullptr, Wout, bout, out,
                                       MROWS, DIM, 1);
    }
}

// round 12
// speedup vs baseline: 1.7562x; 1.2307x over previous
#include <cuda_runtime.h>
#include <cuda_bf16.h>
#include <cstdint>
#include <math.h>

// Problem constants (fixed by setup_inputs)
#define Bb    8
#define Hh    8
#define NSP   196
#define NTOK  3137
#define DIM   512
#define QKVD  1536
#define MROWS 25096        // Bb * NTOK

// -------------------- scratch (__device__ globals, alloc-free) --------------
// RULE (learned R4-R11): these are referenced ONLY from device code; never
// passed as kernel arguments from host (host-side symbol address is a host
// shadow; with GB300 ATS that silently writes host RAM instead of faulting).
__device__ float         g_qkv [38547456];   // MROWS * QKVD fp32
__device__ __nv_bfloat16 g_xhi [12849152];   // x split       [MROWS,512]
__device__ __nv_bfloat16 g_xlo [12849152];
__device__ __nv_bfloat16 g_ahi [12849152];   // attn out split[MROWS,512]
__device__ __nv_bfloat16 g_alo [12849152];
__device__ __nv_bfloat16 g_wqT_hi[786432];   // Wqkv^T [1536,512]
__device__ __nv_bfloat16 g_wqT_lo[786432];
__device__ __nv_bfloat16 g_woT_hi[262144];   // Wout^T [512,512]
__device__ __nv_bfloat16 g_woT_lo[262144];
__device__ float g_clsm[512];
__device__ float g_clss[512];
__device__ float g_clso[32768];

// -------------------- PTX helpers (sm_80-baseline only) ---------------------
__device__ __forceinline__ uint32_t smem_u32(const void* p) {
    uint32_t a;
    asm("{ .reg .u64 t; cvta.to.shared.u64 t, %1; cvt.u32.u64 %0, t; }"
        : "=r"(a) : "l"(p));
    return a;
}
__device__ __forceinline__ uint32_t lds32(uint32_t a) {
    uint32_t v;
    asm volatile("ld.shared.b32 %0, [%1];" : "=r"(v) : "r"(a));
    return v;
}
__device__ __forceinline__ void sts128(uint32_t a, uint4 v) {
    asm volatile("st.shared.v4.b32 [%0], {%1,%2,%3,%4};"
                 :: "r"(a), "r"(v.x), "r"(v.y), "r"(v.z), "r"(v.w) : "memory");
}
__device__ __forceinline__ void mma_bf16(float* c, const uint32_t* a,
                                         uint32_t b0, uint32_t b1) {
    asm volatile(
        "mma.sync.aligned.m16n8k16.row.col.f32.bf16.bf16.f32 "
        "{%0,%1,%2,%3}, {%4,%5,%6,%7}, {%8,%9}, {%0,%1,%2,%3};"
        : "+f"(c[0]), "+f"(c[1]), "+f"(c[2]), "+f"(c[3])
        : "r"(a[0]), "r"(a[1]), "r"(a[2]), "r"(a[3]), "r"(b0), "r"(b1));
}
__device__ __forceinline__ void split_write(float v, __nv_bfloat16* hi,
                                            __nv_bfloat16* lo, size_t i) {
    __nv_bfloat16 h = __float2bfloat16(v);
    hi[i] = h;
    lo[i] = __float2bfloat16(v - __bfloat162float(h));
}

// -------------------- split x into hi/lo bf16 (device-ref globals) ----------
__global__ __launch_bounds__(256)
void xsplit_kernel(const float* __restrict__ x) {
    size_t i = ((size_t)blockIdx.x * 256 + threadIdx.x) * 4;
    float4 v = *reinterpret_cast<const float4*>(x + i);
    split_write(v.x, g_xhi, g_xlo, i + 0);
    split_write(v.y, g_xhi, g_xlo, i + 1);
    split_write(v.z, g_xhi, g_xlo, i + 2);
    split_write(v.w, g_xhi, g_xlo, i + 3);
}

// ------------- transpose+split weights: W[K,N] -> T[N,K] (mode-selected) ----
__global__ __launch_bounds__(256)
void wsplit_kernel(const float* __restrict__ W, int K, int N, int mode) {
    __nv_bfloat16* Thi = (mode == 0) ? g_wqT_hi : g_woT_hi;
    __nv_bfloat16* Tlo = (mode == 0) ? g_wqT_lo : g_woT_lo;
    __shared__ float t[32][33];
    int n0 = blockIdx.x * 32, k0 = blockIdx.y * 32;
    int tx = threadIdx.x & 31, ty = threadIdx.x >> 5;   // 32 x 8
    #pragma unroll
    for (int i = 0; i < 4; i++) {
        int k = k0 + ty + i * 8;
        t[ty + i * 8][tx] = W[(size_t)k * N + n0 + tx];
    }
    __syncthreads();
    #pragma unroll
    for (int i = 0; i < 4; i++) {
        int n = n0 + ty + i * 8;
        float v = t[tx][ty + i * 8];
        split_write(v, Thi, Tlo, (size_t)n * K + k0 + tx);
    }
}

// -------------------- mma.sync GEMM (bf16 presplit staging) -----------------
// C[M,Nc] = (Ahi+Alo) @ (Bhi+Blo)^T (+bias). 3-term mma, fp32 accum.
// 128x128 tile, k-step 16, double-buffered static smem = 40960 B.
// Row layout (80B pitch): [16 bf16 hi (32B) | 16 bf16 lo (32B) | 16B pad].
// Fragment LDS bank walk: word = (20*row + tq) mod 32 is a permutation over
// 8 consecutive rows x 4 tq -> conflict-free.
#define ROWB   80
#define B_OFF  10240              // 128 rows * 80B
#define STAGEB 20480              // A + B

__global__ __launch_bounds__(256)
void gemm_mma_kernel(const float* __restrict__ bias, float* __restrict__ Cext,
                     int M, int Nc, int mode)
{
    const __nv_bfloat16 *Ahi, *Alo, *Bh, *Bl;
    float* C;
    if (mode == 0) {
        Ahi = g_xhi; Alo = g_xlo; Bh = g_wqT_hi; Bl = g_wqT_lo;
        C = g_qkv;
    } else {
        Ahi = g_ahi; Alo = g_alo; Bh = g_woT_hi; Bl = g_woT_lo;
        C = Cext;
    }

    __shared__ uint32_t smem[2 * STAGEB / 4];   // 40960 B static
    uint32_t sb = smem_u32(smem);

    const int tid = threadIdx.x, wid = tid >> 5, lane = tid & 31;
    const int warpM = wid >> 2, warpN = wid & 3;
    const int gq = lane >> 2, tq = lane & 3;
    const int rowBase = blockIdx.y * 128, colBase = blockIdx.x * 128;

    // staging: thread -> (row = tid>>1, k-half = tid&1), 8 bf16 = 16B each
    const int srow = tid >> 1, skh = tid & 1;
    const int agr = min(rowBase + srow, M - 1);
    const size_t aoffg = (size_t)agr * DIM + skh * 8;
    const size_t boffg = (size_t)(colBase + srow) * DIM + skh * 8;
    const uint32_t soff = (uint32_t)srow * ROWB + (uint32_t)skh * 16;

    float acc[4][4][4];
    #pragma unroll
    for (int i = 0; i < 4; i++)
        #pragma unroll
        for (int j = 0; j < 4; j++)
            #pragma unroll
            for (int e = 0; e < 4; e++) acc[i][j][e] = 0.f;

    uint4 vah, val, vbh, vbl;
    vah = *reinterpret_cast<const uint4*>(Ahi + aoffg);
    val = *reinterpret_cast<const uint4*>(Alo + aoffg);
    vbh = *reinterpret_cast<const uint4*>(Bh + boffg);
    vbl = *reinterpret_cast<const uint4*>(Bl + boffg);
    sts128(sb + soff,              vah);
    sts128(sb + soff + 32,         val);
    sts128(sb + soff + B_OFF,      vbh);
    sts128(sb + soff + B_OFF + 32, vbl);

    const int nIter = DIM / 16;   // 32
    for (int it = 0; it < nIter; it++) {
        if (it + 1 < nIter) {
            int k0 = (it + 1) * 16;
            vah = *reinterpret_cast<const uint4*>(Ahi + aoffg + k0);
            val = *reinterpret_cast<const uint4*>(Alo + aoffg + k0);
            vbh = *reinterpret_cast<const uint4*>(Bh + boffg + k0);
            vbl = *reinterpret_cast<const uint4*>(Bl + boffg + k0);
        }
        __syncthreads();          // buffer (it&1) written; prior reads done

        uint32_t stg = sb + (uint32_t)(it & 1) * STAGEB;
        // A fragments (hi at row+{0,16}, lo at row+{32,48})
        uint32_t ah[4][4], al[4][4];
        uint32_t abase = stg + (uint32_t)(warpM * 64 + gq) * ROWB + tq * 4;
        #pragma unroll
        for (int mf = 0; mf < 4; mf++) {
            uint32_t ba = abase + (uint32_t)(mf * 16) * ROWB;
            ah[mf][0] = lds32(ba);
            ah[mf][1] = lds32(ba + 8 * ROWB);
            ah[mf][2] = lds32(ba + 16);
            ah[mf][3] = lds32(ba + 8 * ROWB + 16);
            al[mf][0] = lds32(ba + 32);
            al[mf][1] = lds32(ba + 8 * ROWB + 32);
            al[mf][2] = lds32(ba + 48);
            al[mf][3] = lds32(ba + 8 * ROWB + 48);
        }
        // B fragments ([n][k] rows, symmetric to A)
        uint32_t bh[4][2], bl[4][2];
        uint32_t bbase = stg + B_OFF + (uint32_t)(warpN * 32 + gq) * ROWB + tq * 4;
        #pragma unroll
        for (int nf = 0; nf < 4; nf++) {
            uint32_t bb = bbase + (uint32_t)(nf * 8) * ROWB;
            bh[nf][0] = lds32(bb);
            bh[nf][1] = lds32(bb + 16);
            bl[nf][0] = lds32(bb + 32);
            bl[nf][1] = lds32(bb + 48);
        }
        // store next slab to the OTHER buffer (overlaps MMA)
        if (it + 1 < nIter) {
            uint32_t st = sb + (uint32_t)((it + 1) & 1) * STAGEB;
            sts128(st + soff,              vah);
            sts128(st + soff + 32,         val);
            sts128(st + soff + B_OFF,      vbh);
            sts128(st + soff + B_OFF + 32, vbl);
        }
        // MMAs (3-term split)
        #pragma unroll
        for (int mf = 0; mf < 4; mf++)
            #pragma unroll
            for (int nf = 0; nf < 4; nf++) {
                mma_bf16(acc[mf][nf], ah[mf], bh[nf][0], bh[nf][1]);
                mma_bf16(acc[mf][nf], ah[mf], bl[nf][0], bl[nf][1]);
                mma_bf16(acc[mf][nf], al[mf], bh[nf][0], bh[nf][1]);
            }
    }

    // epilogue: direct float2 stores (documented C fragment layout)
    #pragma unroll
    for (int nf = 0; nf < 4; nf++) {
        int col = colBase + warpN * 32 + nf * 8 + tq * 2;
        float2 bv = make_float2(0.f, 0.f);
        if (bias) bv = *reinterpret_cast<const float2*>(&bias[col]);
        #pragma unroll
        for (int mf = 0; mf < 4; mf++) {
            int r0 = rowBase + warpM * 64 + mf * 16 + gq;
            if (r0 < M) {
                float2 v = make_float2(acc[mf][nf][0] + bv.x,
                                       acc[mf][nf][1] + bv.y);
                *reinterpret_cast<float2*>(&C[(size_t)r0 * Nc + col]) = v;
            }
            int r1 = r0 + 8;
            if (r1 < M) {
                float2 v = make_float2(acc[mf][nf][2] + bv.x,
                                       acc[mf][nf][3] + bv.y);
                *reinterpret_cast<float2*>(&C[(size_t)r1 * Nc + col]) = v;
            }
        }
    }
}

// -------------------- CLS attention: chunked partials + merge ---------------
#define CLS_CH 393     // ceil(3137/8)

__global__ __launch_bounds__(256)
void cls_partial_kernel()
{
    __shared__ float sq[64];
    __shared__ float sc[CLS_CH];
    __shared__ float red[256];

    const int bx = blockIdx.x;           // bh*8 + c
    const int bh = bx >> 3, c = bx & 7;
    const int b = bh / Hh, h = bh % Hh;
    const int tid = threadIdx.x;
    const float scale = 0.125f;
    const int t0 = c * CLS_CH, t1 = min(NTOK, t0 + CLS_CH);

    if (tid < 64)
        sq[tid] = g_qkv[(size_t)(b * NTOK) * QKVD + h * 64 + tid] * scale;
    __syncthreads();

    float lmax = -1e30f;
    for (int t = t0 + tid; t < t1; t += 256) {
        const float4* kp = reinterpret_cast<const float4*>(
            &g_qkv[(size_t)(b * NTOK + t) * QKVD + DIM + h * 64]);
        float d0 = 0.f, d1 = 0.f, d2 = 0.f, d3 = 0.f;
        #pragma unroll
        for (int i = 0; i < 16; i++) {
            float4 kv = kp[i];
            d0 += sq[4*i+0] * kv.x; d1 += sq[4*i+1] * kv.y;
            d2 += sq[4*i+2] * kv.z; d3 += sq[4*i+3] * kv.w;
        }
        float dot = (d0 + d1) + (d2 + d3);
        sc[t - t0] = dot;
        lmax = fmaxf(lmax, dot);
    }
    red[tid] = lmax; __syncthreads();
    for (int s = 128; s > 0; s >>= 1) {
        if (tid < s) red[tid] = fmaxf(red[tid], red[tid + s]);
        __syncthreads();
    }
    const float m = red[0];
    __syncthreads();

    float lsum = 0.f;
    for (int t = t0 + tid; t < t1; t += 256) {
        float e = expf(sc[t - t0] - m);
        sc[t - t0] = e;
        lsum += e;
    }
    red[tid] = lsum; __syncthreads();
    for (int s = 128; s > 0; s >>= 1) {
        if (tid < s) red[tid] += red[tid + s];
        __syncthreads();
    }
    const float ssum = red[0];
    __syncthreads();

    const int d = tid & 63, chunk = tid >> 6;
    float acc = 0.f;
    for (int t = t0 + chunk; t < t1; t += 4)
        acc += sc[t - t0] * g_qkv[(size_t)(b * NTOK + t) * QKVD + 2 * DIM + h * 64 + d];
    red[tid] = acc; __syncthreads();
    if (chunk == 0) {
        float tot = acc + red[tid + 64] + red[tid + 128] + red[tid + 192];
        g_clso[bx * 64 + d] = tot;
        if (d == 0) { g_clsm[bx] = m; g_clss[bx] = ssum; }
    }
}

__global__ __launch_bounds__(64)
void cls_merge_kernel()
{
    const int bh = blockIdx.x;
    const int b = bh / Hh, h = bh % Hh;
    const int d = threadIdx.x;

    float M = -1e30f;
    #pragma unroll
    for (int c = 0; c < 8; c++) M = fmaxf(M, g_clsm[bh * 8 + c]);
    float S = 0.f, O = 0.f;
    #pragma unroll
    for (int c = 0; c < 8; c++) {
        float w = expf(g_clsm[bh * 8 + c] - M);
        S += g_clss[bh * 8 + c] * w;
        O += g_clso[(bh * 8 + c) * 64 + d] * w;
    }
    split_write(O / S, g_ahi, g_alo, (size_t)(b * NTOK) * DIM + h * 64 + d);
}

// -------------------- time attention ---------------------------------------
__global__ __launch_bounds__(128)
void time_attn_kernel()
{
    __shared__ float Qs[16][65];
    __shared__ float Ks[17][65];
    __shared__ float Vs[17][65];

    const int s  = blockIdx.x;
    const int bh = s / NSP, j = s % NSP;
    const int b  = bh / Hh, h = bh % Hh;
    const int tid = threadIdx.x;
    const float scale = 0.125f;

    for (int idx = tid; idx < 16 * 16; idx += 128) {
        int i = idx >> 4, d4 = (idx & 15) * 4;
        int t = 1 + i * NSP + j;
        float4 q = *reinterpret_cast<const float4*>(
            &g_qkv[(size_t)(b * NTOK + t) * QKVD + h * 64 + d4]);
        Qs[i][d4+0] = q.x * scale; Qs[i][d4+1] = q.y * scale;
        Qs[i][d4+2] = q.z * scale; Qs[i][d4+3] = q.w * scale;
    }
    for (int idx = tid; idx < 17 * 16; idx += 128) {
        int key = idx >> 4, d4 = (idx & 15) * 4;
        int t = (key == 0) ? 0 : 1 + (key - 1) * NSP + j;
        size_t base = (size_t)(b * NTOK + t) * QKVD + h * 64 + d4;
        float4 kv = *reinterpret_cast<const float4*>(&g_qkv[base + DIM]);
        float4 vv = *reinterpret_cast<const float4*>(&g_qkv[base + 2 * DIM]);
        Ks[key][d4+0] = kv.x; Ks[key][d4+1] = kv.y;
        Ks[key][d4+2] = kv.z; Ks[key][d4+3] = kv.w;
        Vs[key][d4+0] = vv.x; Vs[key][d4+1] = vv.y;
        Vs[key][d4+2] = vv.z; Vs[key][d4+3] = vv.w;
    }
    __syncthreads();

    const int w = tid >> 5, lane = tid & 31;
    for (int qi = w; qi < 16; qi += 4) {
        float scv = -1e30f;
        if (lane < 17) {
            float a = 0.f;
            #pragma unroll
            for (int d = 0; d < 64; d++) a += Qs[qi][d] * Ks[lane][d];
            scv = a;
        }
        float m = scv;
        #pragma unroll
        for (int o = 16; o > 0; o >>= 1)
            m = fmaxf(m, __shfl_xor_sync(0xffffffffu, m, o));
        float e = (lane < 17) ? expf(scv - m) : 0.f;
        float ssum = e;
        #pragma unroll
        for (int o = 16; o > 0; o >>= 1)
            ssum += __shfl_xor_sync(0xffffffffu, ssum, o);
        float p = e / ssum;

        float a0 = 0.f, a1 = 0.f;
        #pragma unroll
        for (int kk = 0; kk < 17; kk++) {
            float pj = __shfl_sync(0xffffffffu, p, kk);
            a0 += pj * Vs[kk][lane];
            a1 += pj * Vs[kk][lane + 32];
        }
        int t = 1 + qi * NSP + j;
        size_t ob = (size_t)(b * NTOK + t) * DIM + h * 64;
        split_write(a0, g_ahi, g_alo, ob + lane);
        split_write(a1, g_ahi, g_alo, ob + lane + 32);
    }
}

// -------------------- launch -----------------------------------------------
extern "C" void kernel_launch(void* const* d_in, const int* in_sizes, int n_in,
                              void* d_out, int out_size)
{
    const float* x    = (const float*)d_in[0];   // [B, N, 512]
    const float* Wqkv = (const float*)d_in[1];   // [512, 1536]
    const float* Wout = (const float*)d_in[2];   // [512, 512]
    const float* bout = (const float*)d_in[3];   // [512]
    float* out = (float*)d_out;

    // 0) pre-split inputs/weights (globals selected inside kernels)
    xsplit_kernel<<<(MROWS * DIM) / 1024, 256>>>(x);
    {
        dim3 g1(QKVD / 32, DIM / 32);
        wsplit_kernel<<<g1, 256>>>(Wqkv, DIM, QKVD, 0);
        dim3 g2(DIM / 32, DIM / 32);
        wsplit_kernel<<<g2, 256>>>(Wout, DIM, DIM, 1);
    }
    // 1) qkv = x @ Wqkv -> g_qkv
    {
        dim3 grid(QKVD / 128, (MROWS + 127) / 128);
        gemm_mma_kernel<<<grid, 256>>>(nullptr, nullptr, MROWS, QKVD, 0);
    }
    // 2) attention -> g_ahi/g_alo
    cls_partial_kernel<<<512, 256>>>();
    cls_merge_kernel<<<Bb * Hh, 64>>>();
    time_attn_kernel<<<Bb * Hh * NSP, 128>>>();
    // 3) out = attn @ Wout + bias
    {
        dim3 grid(DIM / 128, (MROWS + 127) / 128);
        gemm_mma_kernel<<<grid, 256>>>(bout, out, MROWS, DIM, 1);
    }
}

// round 13
// speedup vs baseline: 1.8415x; 1.0485x over previous
#include <cuda_runtime.h>
#include <cuda_bf16.h>
#include <cstdint>
#include <math.h>

// Problem constants (fixed by setup_inputs)
#define Bb    8
#define Hh    8
#define NSP   196
#define NTOK  3137
#define DIM   512
#define QKVD  1536
#define MROWS 25096        // Bb * NTOK

// -------------------- scratch (__device__ globals, alloc-free) --------------
// RULE (R4-R11): referenced ONLY from device code; never passed as kernel
// arguments from host (host shadow symbol + GB300 ATS = silent host write).
__device__ float         g_qkv [38547456];   // MROWS * QKVD fp32
__device__ __nv_bfloat16 g_xhi [12849152];
__device__ __nv_bfloat16 g_xlo [12849152];
__device__ __nv_bfloat16 g_ahi [12849152];
__device__ __nv_bfloat16 g_alo [12849152];
__device__ __nv_bfloat16 g_wqT_hi[786432];   // Wqkv^T [1536,512]
__device__ __nv_bfloat16 g_wqT_lo[786432];
__device__ __nv_bfloat16 g_woT_hi[262144];   // Wout^T [512,512]
__device__ __nv_bfloat16 g_woT_lo[262144];
__device__ float g_clsm[512];
__device__ float g_clss[512];
__device__ float g_clso[32768];

// -------------------- PTX helpers (sm_80-baseline only) ---------------------
__device__ __forceinline__ uint32_t smem_u32(const void* p) {
    uint32_t a;
    asm("{ .reg .u64 t; cvta.to.shared.u64 t, %1; cvt.u32.u64 %0, t; }"
        : "=r"(a) : "l"(p));
    return a;
}
__device__ __forceinline__ void sts128(uint32_t a, uint4 v) {
    asm volatile("st.shared.v4.b32 [%0], {%1,%2,%3,%4};"
                 :: "r"(a), "r"(v.x), "r"(v.y), "r"(v.z), "r"(v.w) : "memory");
}
__device__ __forceinline__ void ldmx4(uint32_t* r, uint32_t addr) {
    asm volatile("ldmatrix.sync.aligned.m8n8.x4.shared.b16 {%0,%1,%2,%3}, [%4];"
                 : "=r"(r[0]), "=r"(r[1]), "=r"(r[2]), "=r"(r[3]) : "r"(addr));
}
__device__ __forceinline__ void mma_bf16(float* c, const uint32_t* a,
                                         uint32_t b0, uint32_t b1) {
    asm volatile(
        "mma.sync.aligned.m16n8k16.row.col.f32.bf16.bf16.f32 "
        "{%0,%1,%2,%3}, {%4,%5,%6,%7}, {%8,%9}, {%0,%1,%2,%3};"
        : "+f"(c[0]), "+f"(c[1]), "+f"(c[2]), "+f"(c[3])
        : "r"(a[0]), "r"(a[1]), "r"(a[2]), "r"(a[3]), "r"(b0), "r"(b1));
}
__device__ __forceinline__ void split_write(float v, __nv_bfloat16* hi,
                                            __nv_bfloat16* lo, size_t i) {
    __nv_bfloat16 h = __float2bfloat16(v);
    hi[i] = h;
    lo[i] = __float2bfloat16(v - __bfloat162float(h));
}

// -------------------- split x into hi/lo bf16 -------------------------------
__global__ __launch_bounds__(256)
void xsplit_kernel(const float* __restrict__ x) {
    size_t i = ((size_t)blockIdx.x * 256 + threadIdx.x) * 4;
    float4 v = *reinterpret_cast<const float4*>(x + i);
    split_write(v.x, g_xhi, g_xlo, i + 0);
    split_write(v.y, g_xhi, g_xlo, i + 1);
    split_write(v.z, g_xhi, g_xlo, i + 2);
    split_write(v.w, g_xhi, g_xlo, i + 3);
}

// ------------- transpose+split weights: W[K,N] -> T[N,K] (mode-selected) ----
__global__ __launch_bounds__(256)
void wsplit_kernel(const float* __restrict__ W, int K, int N, int mode) {
    __nv_bfloat16* Thi = (mode == 0) ? g_wqT_hi : g_woT_hi;
    __nv_bfloat16* Tlo = (mode == 0) ? g_wqT_lo : g_woT_lo;
    __shared__ float t[32][33];
    int n0 = blockIdx.x * 32, k0 = blockIdx.y * 32;
    int tx = threadIdx.x & 31, ty = threadIdx.x >> 5;   // 32 x 8
    #pragma unroll
    for (int i = 0; i < 4; i++) {
        int k = k0 + ty + i * 8;
        t[ty + i * 8][tx] = W[(size_t)k * N + n0 + tx];
    }
    __syncthreads();
    #pragma unroll
    for (int i = 0; i < 4; i++) {
        int n = n0 + ty + i * 8;
        float v = t[tx][ty + i * 8];
        split_write(v, Thi, Tlo, (size_t)n * K + k0 + tx);
    }
}

// -------------------- mma.sync GEMM (ldmatrix + deferred STS) ---------------
// C[M,Nc] = (Ahi+Alo) @ (Bhi+Blo)^T (+bias). 3-term mma, fp32 accum.
// 128x128 tile, k-step 16, double-buffered static smem = 40960 B.
// Row layout (80B pitch): [16 bf16 hi (32B) | 16 bf16 lo (32B) | 16B pad].
// ldmatrix phases read 8 rows @80B stride: banks 20r mod 32 cover all 32
// banks -> conflict-free.
// Loop order: LDG(it+1) -> sync -> ldmatrix -> MMA -> STS(it+1): LDG latency
// is hidden under the MMA burst instead of blocking it.
#define ROWB   80
#define B_OFF  10240              // 128 rows * 80B
#define STAGEB 20480              // A + B

__global__ __launch_bounds__(256)
void gemm_mma_kernel(const float* __restrict__ bias, float* __restrict__ Cext,
                     int M, int Nc, int mode)
{
    const __nv_bfloat16 *Ahi, *Alo, *Bh, *Bl;
    float* C;
    if (mode == 0) {
        Ahi = g_xhi; Alo = g_xlo; Bh = g_wqT_hi; Bl = g_wqT_lo;
        C = g_qkv;
    } else {
        Ahi = g_ahi; Alo = g_alo; Bh = g_woT_hi; Bl = g_woT_lo;
        C = Cext;
    }

    __shared__ uint32_t smem[2 * STAGEB / 4];   // 40960 B static
    uint32_t sb = smem_u32(smem);

    const int tid = threadIdx.x, wid = tid >> 5, lane = tid & 31;
    const int warpM = wid >> 2, warpN = wid & 3;
    const int gq = lane >> 2, tq = lane & 3;
    const int rowBase = blockIdx.y * 128, colBase = blockIdx.x * 128;

    // staging: thread -> (row = tid>>1, k-half = tid&1), 8 bf16 = 16B each
    const int srow = tid >> 1, skh = tid & 1;
    const int agr = min(rowBase + srow, M - 1);
    const size_t aoffg = (size_t)agr * DIM + skh * 8;
    const size_t boffg = (size_t)(colBase + srow) * DIM + skh * 8;
    const uint32_t soff = (uint32_t)srow * ROWB + (uint32_t)skh * 16;

    // ldmatrix lane addressing
    const int arow  = lane & 15;            // A: row within 16-row tile
    const uint32_t aksel = (uint32_t)(lane >> 4) * 16;   // k half (bytes)
    const int brow  = lane & 7;             // B: row within 8-row group
    const uint32_t bksel = (uint32_t)((lane >> 3) & 1) * 16;
    const int bnsel = lane >> 4;            // which 8-n group of the pair

    float acc[4][4][4];
    #pragma unroll
    for (int i = 0; i < 4; i++)
        #pragma unroll
        for (int j = 0; j < 4; j++)
            #pragma unroll
            for (int e = 0; e < 4; e++) acc[i][j][e] = 0.f;

    uint4 vah, val, vbh, vbl;
    vah = *reinterpret_cast<const uint4*>(Ahi + aoffg);
    val = *reinterpret_cast<const uint4*>(Alo + aoffg);
    vbh = *reinterpret_cast<const uint4*>(Bh + boffg);
    vbl = *reinterpret_cast<const uint4*>(Bl + boffg);
    sts128(sb + soff,              vah);
    sts128(sb + soff + 32,         val);
    sts128(sb + soff + B_OFF,      vbh);
    sts128(sb + soff + B_OFF + 32, vbl);

    const int nIter = DIM / 16;   // 32
    for (int it = 0; it < nIter; it++) {
        // prefetch next slab into registers (consumed AFTER the MMAs)
        if (it + 1 < nIter) {
            int k0 = (it + 1) * 16;
            vah = *reinterpret_cast<const uint4*>(Ahi + aoffg + k0);
            val = *reinterpret_cast<const uint4*>(Alo + aoffg + k0);
            vbh = *reinterpret_cast<const uint4*>(Bh + boffg + k0);
            vbl = *reinterpret_cast<const uint4*>(Bl + boffg + k0);
        }
        __syncthreads();          // buffer (it&1) fully written; prior reads done

        uint32_t stg = sb + (uint32_t)(it & 1) * STAGEB;
        // A fragments via ldmatrix.x4 (reg order == mma A fragment order)
        uint32_t ah[4][4], al[4][4];
        {
            uint32_t abase = stg + (uint32_t)(warpM * 64 + arow) * ROWB + aksel;
            #pragma unroll
            for (int mf = 0; mf < 4; mf++) {
                ldmx4(ah[mf], abase + (uint32_t)mf * (16 * ROWB));
                ldmx4(al[mf], abase + (uint32_t)mf * (16 * ROWB) + 32);
            }
        }
        // B fragments via ldmatrix.x4: one per nf-pair, regs
        // {b[2p][0], b[2p][1], b[2p+1][0], b[2p+1][1]}
        uint32_t bhf[2][4], blf[2][4];
        {
            uint32_t bbase = stg + B_OFF
                           + (uint32_t)(warpN * 32 + bnsel * 8 + brow) * ROWB
                           + bksel;
            #pragma unroll
            for (int p = 0; p < 2; p++) {
                ldmx4(bhf[p], bbase + (uint32_t)p * (16 * ROWB));
                ldmx4(blf[p], bbase + (uint32_t)p * (16 * ROWB) + 32);
            }
        }
        // MMAs (3-term split)
        #pragma unroll
        for (int mf = 0; mf < 4; mf++)
            #pragma unroll
            for (int nf = 0; nf < 4; nf++) {
                int p = nf >> 1, q = nf & 1;
                mma_bf16(acc[mf][nf], ah[mf], bhf[p][q*2], bhf[p][q*2+1]);
                mma_bf16(acc[mf][nf], ah[mf], blf[p][q*2], blf[p][q*2+1]);
                mma_bf16(acc[mf][nf], al[mf], bhf[p][q*2], bhf[p][q*2+1]);
            }
        // store next slab to the OTHER buffer (LDG latency now hidden by MMA)
        if (it + 1 < nIter) {
            uint32_t st = sb + (uint32_t)((it + 1) & 1) * STAGEB;
            sts128(st + soff,              vah);
            sts128(st + soff + 32,         val);
            sts128(st + soff + B_OFF,      vbh);
            sts128(st + soff + B_OFF + 32, vbl);
        }
    }

    // epilogue: direct float2 stores (documented C fragment layout)
    #pragma unroll
    for (int nf = 0; nf < 4; nf++) {
        int col = colBase + warpN * 32 + nf * 8 + tq * 2;
        float2 bv = make_float2(0.f, 0.f);
        if (bias) bv = *reinterpret_cast<const float2*>(&bias[col]);
        #pragma unroll
        for (int mf = 0; mf < 4; mf++) {
            int r0 = rowBase + warpM * 64 + mf * 16 + gq;
            if (r0 < M) {
                float2 v = make_float2(acc[mf][nf][0] + bv.x,
                                       acc[mf][nf][1] + bv.y);
                *reinterpret_cast<float2*>(&C[(size_t)r0 * Nc + col]) = v;
            }
            int r1 = r0 + 8;
            if (r1 < M) {
                float2 v = make_float2(acc[mf][nf][2] + bv.x,
                                       acc[mf][nf][3] + bv.y);
                *reinterpret_cast<float2*>(&C[(size_t)r1 * Nc + col]) = v;
            }
        }
    }
}

// -------------------- CLS attention: chunked partials + merge ---------------
#define CLS_CH 393     // ceil(3137/8)

__global__ __launch_bounds__(256)
void cls_partial_kernel()
{
    __shared__ float sq[64];
    __shared__ float sc[CLS_CH];
    __shared__ float red[256];

    const int bx = blockIdx.x;           // bh*8 + c
    const int bh = bx >> 3, c = bx & 7;
    const int b = bh / Hh, h = bh % Hh;
    const int tid = threadIdx.x;
    const float scale = 0.125f;
    const int t0 = c * CLS_CH, t1 = min(NTOK, t0 + CLS_CH);

    if (tid < 64)
        sq[tid] = g_qkv[(size_t)(b * NTOK) * QKVD + h * 64 + tid] * scale;
    __syncthreads();

    float lmax = -1e30f;
    for (int t = t0 + tid; t < t1; t += 256) {
        const float4* kp = reinterpret_cast<const float4*>(
            &g_qkv[(size_t)(b * NTOK + t) * QKVD + DIM + h * 64]);
        float d0 = 0.f, d1 = 0.f, d2 = 0.f, d3 = 0.f;
        #pragma unroll
        for (int i = 0; i < 16; i++) {
            float4 kv = kp[i];
            d0 += sq[4*i+0] * kv.x; d1 += sq[4*i+1] * kv.y;
            d2 += sq[4*i+2] * kv.z; d3 += sq[4*i+3] * kv.w;
        }
        float dot = (d0 + d1) + (d2 + d3);
        sc[t - t0] = dot;
        lmax = fmaxf(lmax, dot);
    }
    red[tid] = lmax; __syncthreads();
    for (int s = 128; s > 0; s >>= 1) {
        if (tid < s) red[tid] = fmaxf(red[tid], red[tid + s]);
        __syncthreads();
    }
    const float m = red[0];
    __syncthreads();

    float lsum = 0.f;
    for (int t = t0 + tid; t < t1; t += 256) {
        float e = expf(sc[t - t0] - m);
        sc[t - t0] = e;
        lsum += e;
    }
    red[tid] = lsum; __syncthreads();
    for (int s = 128; s > 0; s >>= 1) {
        if (tid < s) red[tid] += red[tid + s];
        __syncthreads();
    }
    const float ssum = red[0];
    __syncthreads();

    const int d = tid & 63, chunk = tid >> 6;
    float acc = 0.f;
    for (int t = t0 + chunk; t < t1; t += 4)
        acc += sc[t - t0] * g_qkv[(size_t)(b * NTOK + t) * QKVD + 2 * DIM + h * 64 + d];
    red[tid] = acc; __syncthreads();
    if (chunk == 0) {
        float tot = acc + red[tid + 64] + red[tid + 128] + red[tid + 192];
        g_clso[bx * 64 + d] = tot;
        if (d == 0) { g_clsm[bx] = m; g_clss[bx] = ssum; }
    }
}

__global__ __launch_bounds__(64)
void cls_merge_kernel()
{
    const int bh = blockIdx.x;
    const int b = bh / Hh, h = bh % Hh;
    const int d = threadIdx.x;

    float M = -1e30f;
    #pragma unroll
    for (int c = 0; c < 8; c++) M = fmaxf(M, g_clsm[bh * 8 + c]);
    float S = 0.f, O = 0.f;
    #pragma unroll
    for (int c = 0; c < 8; c++) {
        float w = expf(g_clsm[bh * 8 + c] - M);
        S += g_clss[bh * 8 + c] * w;
        O += g_clso[(bh * 8 + c) * 64 + d] * w;
    }
    split_write(O / S, g_ahi, g_alo, (size_t)(b * NTOK) * DIM + h * 64 + d);
}

// -------------------- time attention ---------------------------------------
__global__ __launch_bounds__(128)
void time_attn_kernel()
{
    __shared__ float Qs[16][65];
    __shared__ float Ks[17][65];
    __shared__ float Vs[17][65];

    const int s  = blockIdx.x;
    const int bh = s / NSP, j = s % NSP;
    const int b  = bh / Hh, h = bh % Hh;
    const int tid = threadIdx.x;
    const float scale = 0.125f;

    for (int idx = tid; idx < 16 * 16; idx += 128) {
        int i = idx >> 4, d4 = (idx & 15) * 4;
        int t = 1 + i * NSP + j;
        float4 q = *reinterpret_cast<const float4*>(
            &g_qkv[(size_t)(b * NTOK + t) * QKVD + h * 64 + d4]);
        Qs[i][d4+0] = q.x * scale; Qs[i][d4+1] = q.y * scale;
        Qs[i][d4+2] = q.z * scale; Qs[i][d4+3] = q.w * scale;
    }
    for (int idx = tid; idx < 17 * 16; idx += 128) {
        int key = idx >> 4, d4 = (idx & 15) * 4;
        int t = (key == 0) ? 0 : 1 + (key - 1) * NSP + j;
        size_t base = (size_t)(b * NTOK + t) * QKVD + h * 64 + d4;
        float4 kv = *reinterpret_cast<const float4*>(&g_qkv[base + DIM]);
        float4 vv = *reinterpret_cast<const float4*>(&g_qkv[base + 2 * DIM]);
        Ks[key][d4+0] = kv.x; Ks[key][d4+1] = kv.y;
        Ks[key][d4+2] = kv.z; Ks[key][d4+3] = kv.w;
        Vs[key][d4+0] = vv.x; Vs[key][d4+1] = vv.y;
        Vs[key][d4+2] = vv.z; Vs[key][d4+3] = vv.w;
    }
    __syncthreads();

    const int w = tid >> 5, lane = tid & 31;
    for (int qi = w; qi < 16; qi += 4) {
        float scv = -1e30f;
        if (lane < 17) {
            float a = 0.f;
            #pragma unroll
            for (int d = 0; d < 64; d++) a += Qs[qi][d] * Ks[lane][d];
            scv = a;
        }
        float m = scv;
        #pragma unroll
        for (int o = 16; o > 0; o >>= 1)
            m = fmaxf(m, __shfl_xor_sync(0xffffffffu, m, o));
        float e = (lane < 17) ? expf(scv - m) : 0.f;
        float ssum = e;
        #pragma unroll
        for (int o = 16; o > 0; o >>= 1)
            ssum += __shfl_xor_sync(0xffffffffu, ssum, o);
        float p = e / ssum;

        float a0 = 0.f, a1 = 0.f;
        #pragma unroll
        for (int kk = 0; kk < 17; kk++) {
            float pj = __shfl_sync(0xffffffffu, p, kk);
            a0 += pj * Vs[kk][lane];
            a1 += pj * Vs[kk][lane + 32];
        }
        int t = 1 + qi * NSP + j;
        size_t ob = (size_t)(b * NTOK + t) * DIM + h * 64;
        split_write(a0, g_ahi, g_alo, ob + lane);
        split_write(a1, g_ahi, g_alo, ob + lane + 32);
    }
}

// -------------------- launch -----------------------------------------------
extern "C" void kernel_launch(void* const* d_in, const int* in_sizes, int n_in,
                              void* d_out, int out_size)
{
    const float* x    = (const float*)d_in[0];   // [B, N, 512]
    const float* Wqkv = (const float*)d_in[1];   // [512, 1536]
    const float* Wout = (const float*)d_in[2];   // [512, 512]
    const float* bout = (const float*)d_in[3];   // [512]
    float* out = (float*)d_out;

    // 0) pre-split inputs/weights (globals selected inside kernels)
    xsplit_kernel<<<(MROWS * DIM) / 1024, 256>>>(x);
    {
        dim3 g1(QKVD / 32, DIM / 32);
        wsplit_kernel<<<g1, 256>>>(Wqkv, DIM, QKVD, 0);
        dim3 g2(DIM / 32, DIM / 32);
        wsplit_kernel<<<g2, 256>>>(Wout, DIM, DIM, 1);
    }
    // 1) qkv = x @ Wqkv -> g_qkv
    {
        dim3 grid(QKVD / 128, (MROWS + 127) / 128);
        gemm_mma_kernel<<<grid, 256>>>(nullptr, nullptr, MROWS, QKVD, 0);
    }
    // 2) attention -> g_ahi/g_alo
    cls_partial_kernel<<<512, 256>>>();
    cls_merge_kernel<<<Bb * Hh, 64>>>();
    time_attn_kernel<<<Bb * Hh * NSP, 128>>>();
    // 3) out = attn @ Wout + bias
    {
        dim3 grid(DIM / 128, (MROWS + 127) / 128);
        gemm_mma_kernel<<<grid, 256>>>(bout, out, MROWS, DIM, 1);
    }
}

// round 14
// speedup vs baseline: 2.1064x; 1.1439x over previous
#include <cuda_runtime.h>
#include <cuda_bf16.h>
#include <cstdint>
#include <math.h>

// Problem constants (fixed by setup_inputs)
#define Bb    8
#define Hh    8
#define NSP   196
#define NTOK  3137
#define DIM   512
#define QKVD  1536
#define MROWS 25096        // Bb * NTOK

// -------------------- scratch (__device__ globals, alloc-free) --------------
// RULE (R4-R11): referenced ONLY from device code; never passed as kernel
// arguments from host (host shadow symbol + GB300 ATS = silent host write).
__device__ float         g_qkv [38547456];   // MROWS * QKVD fp32
__device__ __nv_bfloat16 g_xhi [12849152];
__device__ __nv_bfloat16 g_xlo [12849152];
__device__ __nv_bfloat16 g_ahi [12849152];
__device__ __nv_bfloat16 g_alo [12849152];
__device__ __nv_bfloat16 g_wqT_hi[786432];   // Wqkv^T [1536,512]
__device__ __nv_bfloat16 g_wqT_lo[786432];
__device__ __nv_bfloat16 g_woT_hi[262144];   // Wout^T [512,512]
__device__ __nv_bfloat16 g_woT_lo[262144];
__device__ float g_clsm[512];
__device__ float g_clss[512];
__device__ float g_clso[32768];

// -------------------- PTX helpers (sm_80-baseline only) ---------------------
__device__ __forceinline__ uint32_t smem_u32(const void* p) {
    uint32_t a;
    asm("{ .reg .u64 t; cvta.to.shared.u64 t, %1; cvt.u32.u64 %0, t; }"
        : "=r"(a) : "l"(p));
    return a;
}
__device__ __forceinline__ void sts128(uint32_t a, uint4 v) {
    asm volatile("st.shared.v4.b32 [%0], {%1,%2,%3,%4};"
                 :: "r"(a), "r"(v.x), "r"(v.y), "r"(v.z), "r"(v.w) : "memory");
}
__device__ __forceinline__ void ldmx4(uint32_t* r, uint32_t addr) {
    asm volatile("ldmatrix.sync.aligned.m8n8.x4.shared.b16 {%0,%1,%2,%3}, [%4];"
                 : "=r"(r[0]), "=r"(r[1]), "=r"(r[2]), "=r"(r[3]) : "r"(addr));
}
__device__ __forceinline__ void mma_bf16(float* c, const uint32_t* a,
                                         uint32_t b0, uint32_t b1) {
    asm volatile(
        "mma.sync.aligned.m16n8k16.row.col.f32.bf16.bf16.f32 "
        "{%0,%1,%2,%3}, {%4,%5,%6,%7}, {%8,%9}, {%0,%1,%2,%3};"
        : "+f"(c[0]), "+f"(c[1]), "+f"(c[2]), "+f"(c[3])
        : "r"(a[0]), "r"(a[1]), "r"(a[2]), "r"(a[3]), "r"(b0), "r"(b1));
}
__device__ __forceinline__ void split_write(float v, __nv_bfloat16* hi,
                                            __nv_bfloat16* lo, size_t i) {
    __nv_bfloat16 h = __float2bfloat16(v);
    hi[i] = h;
    lo[i] = __float2bfloat16(v - __bfloat162float(h));
}

// -------------------- split x into hi/lo bf16 -------------------------------
__global__ __launch_bounds__(256)
void xsplit_kernel(const float* __restrict__ x) {
    size_t i = ((size_t)blockIdx.x * 256 + threadIdx.x) * 4;
    float4 v = *reinterpret_cast<const float4*>(x + i);
    split_write(v.x, g_xhi, g_xlo, i + 0);
    split_write(v.y, g_xhi, g_xlo, i + 1);
    split_write(v.z, g_xhi, g_xlo, i + 2);
    split_write(v.w, g_xhi, g_xlo, i + 3);
}

// ------------- transpose+split weights: W[K,N] -> T[N,K] (mode-selected) ----
__global__ __launch_bounds__(256)
void wsplit_kernel(const float* __restrict__ W, int K, int N, int mode) {
    __nv_bfloat16* Thi = (mode == 0) ? g_wqT_hi : g_woT_hi;
    __nv_bfloat16* Tlo = (mode == 0) ? g_wqT_lo : g_woT_lo;
    __shared__ float t[32][33];
    int n0 = blockIdx.x * 32, k0 = blockIdx.y * 32;
    int tx = threadIdx.x & 31, ty = threadIdx.x >> 5;   // 32 x 8
    #pragma unroll
    for (int i = 0; i < 4; i++) {
        int k = k0 + ty + i * 8;
        t[ty + i * 8][tx] = W[(size_t)k * N + n0 + tx];
    }
    __syncthreads();
    #pragma unroll
    for (int i = 0; i < 4; i++) {
        int n = n0 + ty + i * 8;
        float v = t[tx][ty + i * 8];
        split_write(v, Thi, Tlo, (size_t)n * K + k0 + tx);
    }
}

// -------------------- mma.sync GEMM (2 CTA/SM, two-pass fragments) ----------
// C[M,Nc] = (Ahi+Alo) @ (Bhi+Blo)^T (+bias). 3-term mma, fp32 accum.
// 128x128 tile, k-step 16, double-buffered static smem = 40960 B.
// Row layout (80B pitch): [16 bf16 hi | 16 bf16 lo | 16B pad]; ldmatrix
// phases over 8 rows @80B cover all 32 banks -> conflict-free.
// Two-pass fragments keep reg peak <=128 so __launch_bounds__(256,2) gives
// 2 CTAs/SM: one block's MMA burst hides the other's barrier/LDSM window.
#define ROWB   80
#define B_OFF  10240              // 128 rows * 80B
#define STAGEB 20480              // A + B

__global__ __launch_bounds__(256, 2)
void gemm_mma_kernel(const float* __restrict__ bias, float* __restrict__ Cext,
                     int M, int Nc, int mode)
{
    const __nv_bfloat16 *Ahi, *Alo, *Bh, *Bl;
    float* C;
    if (mode == 0) {
        Ahi = g_xhi; Alo = g_xlo; Bh = g_wqT_hi; Bl = g_wqT_lo;
        C = g_qkv;
    } else {
        Ahi = g_ahi; Alo = g_alo; Bh = g_woT_hi; Bl = g_woT_lo;
        C = Cext;
    }

    __shared__ uint32_t smem[2 * STAGEB / 4];   // 40960 B static
    uint32_t sb = smem_u32(smem);

    const int tid = threadIdx.x, wid = tid >> 5, lane = tid & 31;
    const int warpM = wid >> 2, warpN = wid & 3;
    const int gq = lane >> 2, tq = lane & 3;
    const int rowBase = blockIdx.y * 128, colBase = blockIdx.x * 128;

    // staging: thread -> (row = tid>>1, k-half = tid&1), 8 bf16 = 16B each
    const int srow = tid >> 1, skh = tid & 1;
    const int agr = min(rowBase + srow, M - 1);
    const size_t aoffg = (size_t)agr * DIM + skh * 8;
    const size_t boffg = (size_t)(colBase + srow) * DIM + skh * 8;
    const uint32_t soff = (uint32_t)srow * ROWB + (uint32_t)skh * 16;

    // ldmatrix lane addressing
    const int arow  = lane & 15;
    const uint32_t aksel = (uint32_t)(lane >> 4) * 16;
    const int brow  = lane & 7;
    const uint32_t bksel = (uint32_t)((lane >> 3) & 1) * 16;
    const int bnsel = lane >> 4;

    float acc[4][4][4];
    #pragma unroll
    for (int i = 0; i < 4; i++)
        #pragma unroll
        for (int j = 0; j < 4; j++)
            #pragma unroll
            for (int e = 0; e < 4; e++) acc[i][j][e] = 0.f;

    uint4 vah, val, vbh, vbl;
    vah = *reinterpret_cast<const uint4*>(Ahi + aoffg);
    val = *reinterpret_cast<const uint4*>(Alo + aoffg);
    vbh = *reinterpret_cast<const uint4*>(Bh + boffg);
    vbl = *reinterpret_cast<const uint4*>(Bl + boffg);
    sts128(sb + soff,              vah);
    sts128(sb + soff + 32,         val);
    sts128(sb + soff + B_OFF,      vbh);
    sts128(sb + soff + B_OFF + 32, vbl);

    const int nIter = DIM / 16;   // 32
    for (int it = 0; it < nIter; it++) {
        // prefetch next slab into registers (consumed AFTER the MMAs)
        if (it + 1 < nIter) {
            int k0 = (it + 1) * 16;
            vah = *reinterpret_cast<const uint4*>(Ahi + aoffg + k0);
            val = *reinterpret_cast<const uint4*>(Alo + aoffg + k0);
            vbh = *reinterpret_cast<const uint4*>(Bh + boffg + k0);
            vbl = *reinterpret_cast<const uint4*>(Bl + boffg + k0);
        }
        __syncthreads();          // buffer (it&1) fully written; prior reads done

        uint32_t stg = sb + (uint32_t)(it & 1) * STAGEB;
        uint32_t abase = stg + (uint32_t)(warpM * 64 + arow) * ROWB + aksel;
        uint32_t bbase = stg + B_OFF
                       + (uint32_t)(warpN * 32 + bnsel * 8 + brow) * ROWB
                       + bksel;

        // B fragments (kept across both passes)
        uint32_t bhf[2][4], blf[2][4];
        #pragma unroll
        for (int p = 0; p < 2; p++) {
            ldmx4(bhf[p], bbase + (uint32_t)p * (16 * ROWB));
            ldmx4(blf[p], bbase + (uint32_t)p * (16 * ROWB) + 32);
        }
        // pass 1: A-hi fragments, terms Ahi*Bhi + Ahi*Blo
        {
            uint32_t af[4][4];
            #pragma unroll
            for (int mf = 0; mf < 4; mf++)
                ldmx4(af[mf], abase + (uint32_t)mf * (16 * ROWB));
            #pragma unroll
            for (int mf = 0; mf < 4; mf++)
                #pragma unroll
                for (int nf = 0; nf < 4; nf++) {
                    int p = nf >> 1, q = nf & 1;
                    mma_bf16(acc[mf][nf], af[mf], bhf[p][q*2], bhf[p][q*2+1]);
                    mma_bf16(acc[mf][nf], af[mf], blf[p][q*2], blf[p][q*2+1]);
                }
        }
        // pass 2: A-lo fragments (reuse regs), term Alo*Bhi
        {
            uint32_t af[4][4];
            #pragma unroll
            for (int mf = 0; mf < 4; mf++)
                ldmx4(af[mf], abase + (uint32_t)mf * (16 * ROWB) + 32);
            #pragma unroll
            for (int mf = 0; mf < 4; mf++)
                #pragma unroll
                for (int nf = 0; nf < 4; nf++) {
                    int p = nf >> 1, q = nf & 1;
                    mma_bf16(acc[mf][nf], af[mf], bhf[p][q*2], bhf[p][q*2+1]);
                }
        }
        // store next slab to the OTHER buffer (LDG latency hidden by MMAs)
        if (it + 1 < nIter) {
            uint32_t st = sb + (uint32_t)((it + 1) & 1) * STAGEB;
            sts128(st + soff,              vah);
            sts128(st + soff + 32,         val);
            sts128(st + soff + B_OFF,      vbh);
            sts128(st + soff + B_OFF + 32, vbl);
        }
    }

    // epilogue: direct float2 stores (documented C fragment layout)
    #pragma unroll
    for (int nf = 0; nf < 4; nf++) {
        int col = colBase + warpN * 32 + nf * 8 + tq * 2;
        float2 bv = make_float2(0.f, 0.f);
        if (bias) bv = *reinterpret_cast<const float2*>(&bias[col]);
        #pragma unroll
        for (int mf = 0; mf < 4; mf++) {
            int r0 = rowBase + warpM * 64 + mf * 16 + gq;
            if (r0 < M) {
                float2 v = make_float2(acc[mf][nf][0] + bv.x,
                                       acc[mf][nf][1] + bv.y);
                *reinterpret_cast<float2*>(&C[(size_t)r0 * Nc + col]) = v;
            }
            int r1 = r0 + 8;
            if (r1 < M) {
                float2 v = make_float2(acc[mf][nf][2] + bv.x,
                                       acc[mf][nf][3] + bv.y);
                *reinterpret_cast<float2*>(&C[(size_t)r1 * Nc + col]) = v;
            }
        }
    }
}

// -------------------- CLS attention: chunked partials + merge ---------------
#define CLS_CH 393     // ceil(3137/8)

__global__ __launch_bounds__(256)
void cls_partial_kernel()
{
    __shared__ float sq[64];
    __shared__ float sc[CLS_CH];
    __shared__ float red[256];

    const int bx = blockIdx.x;           // bh*8 + c
    const int bh = bx >> 3, c = bx & 7;
    const int b = bh / Hh, h = bh % Hh;
    const int tid = threadIdx.x;
    const float scale = 0.125f;
    const int t0 = c * CLS_CH, t1 = min(NTOK, t0 + CLS_CH);

    if (tid < 64)
        sq[tid] = g_qkv[(size_t)(b * NTOK) * QKVD + h * 64 + tid] * scale;
    __syncthreads();

    float lmax = -1e30f;
    for (int t = t0 + tid; t < t1; t += 256) {
        const float4* kp = reinterpret_cast<const float4*>(
            &g_qkv[(size_t)(b * NTOK + t) * QKVD + DIM + h * 64]);
        float d0 = 0.f, d1 = 0.f, d2 = 0.f, d3 = 0.f;
        #pragma unroll
        for (int i = 0; i < 16; i++) {
            float4 kv = kp[i];
            d0 += sq[4*i+0] * kv.x; d1 += sq[4*i+1] * kv.y;
            d2 += sq[4*i+2] * kv.z; d3 += sq[4*i+3] * kv.w;
        }
        float dot = (d0 + d1) + (d2 + d3);
        sc[t - t0] = dot;
        lmax = fmaxf(lmax, dot);
    }
    red[tid] = lmax; __syncthreads();
    for (int s = 128; s > 0; s >>= 1) {
        if (tid < s) red[tid] = fmaxf(red[tid], red[tid + s]);
        __syncthreads();
    }
    const float m = red[0];
    __syncthreads();

    float lsum = 0.f;
    for (int t = t0 + tid; t < t1; t += 256) {
        float e = expf(sc[t - t0] - m);
        sc[t - t0] = e;
        lsum += e;
    }
    red[tid] = lsum; __syncthreads();
    for (int s = 128; s > 0; s >>= 1) {
        if (tid < s) red[tid] += red[tid + s];
        __syncthreads();
    }
    const float ssum = red[0];
    __syncthreads();

    const int d = tid & 63, chunk = tid >> 6;
    float acc = 0.f;
    for (int t = t0 + chunk; t < t1; t += 4)
        acc += sc[t - t0] * g_qkv[(size_t)(b * NTOK + t) * QKVD + 2 * DIM + h * 64 + d];
    red[tid] = acc; __syncthreads();
    if (chunk == 0) {
        float tot = acc + red[tid + 64] + red[tid + 128] + red[tid + 192];
        g_clso[bx * 64 + d] = tot;
        if (d == 0) { g_clsm[bx] = m; g_clss[bx] = ssum; }
    }
}

__global__ __launch_bounds__(64)
void cls_merge_kernel()
{
    const int bh = blockIdx.x;
    const int b = bh / Hh, h = bh % Hh;
    const int d = threadIdx.x;

    float M = -1e30f;
    #pragma unroll
    for (int c = 0; c < 8; c++) M = fmaxf(M, g_clsm[bh * 8 + c]);
    float S = 0.f, O = 0.f;
    #pragma unroll
    for (int c = 0; c < 8; c++) {
        float w = expf(g_clsm[bh * 8 + c] - M);
        S += g_clss[bh * 8 + c] * w;
        O += g_clso[(bh * 8 + c) * 64 + d] * w;
    }
    split_write(O / S, g_ahi, g_alo, (size_t)(b * NTOK) * DIM + h * 64 + d);
}

// -------------------- time attention ---------------------------------------
__global__ __launch_bounds__(128)
void time_attn_kernel()
{
    __shared__ float Qs[16][65];
    __shared__ float Ks[17][65];
    __shared__ float Vs[17][65];

    const int s  = blockIdx.x;
    const int bh = s / NSP, j = s % NSP;
    const int b  = bh / Hh, h = bh % Hh;
    const int tid = threadIdx.x;
    const float scale = 0.125f;

    for (int idx = tid; idx < 16 * 16; idx += 128) {
        int i = idx >> 4, d4 = (idx & 15) * 4;
        int t = 1 + i * NSP + j;
        float4 q = *reinterpret_cast<const float4*>(
            &g_qkv[(size_t)(b * NTOK + t) * QKVD + h * 64 + d4]);
        Qs[i][d4+0] = q.x * scale; Qs[i][d4+1] = q.y * scale;
        Qs[i][d4+2] = q.z * scale; Qs[i][d4+3] = q.w * scale;
    }
    for (int idx = tid; idx < 17 * 16; idx += 128) {
        int key = idx >> 4, d4 = (idx & 15) * 4;
        int t = (key == 0) ? 0 : 1 + (key - 1) * NSP + j;
        size_t base = (size_t)(b * NTOK + t) * QKVD + h * 64 + d4;
        float4 kv = *reinterpret_cast<const float4*>(&g_qkv[base + DIM]);
        float4 vv = *reinterpret_cast<const float4*>(&g_qkv[base + 2 * DIM]);
        Ks[key][d4+0] = kv.x; Ks[key][d4+1] = kv.y;
        Ks[key][d4+2] = kv.z; Ks[key][d4+3] = kv.w;
        Vs[key][d4+0] = vv.x; Vs[key][d4+1] = vv.y;
        Vs[key][d4+2] = vv.z; Vs[key][d4+3] = vv.w;
    }
    __syncthreads();

    const int w = tid >> 5, lane = tid & 31;
    for (int qi = w; qi < 16; qi += 4) {
        float scv = -1e30f;
        if (lane < 17) {
            float a = 0.f;
            #pragma unroll
            for (int d = 0; d < 64; d++) a += Qs[qi][d] * Ks[lane][d];
            scv = a;
        }
        float m = scv;
        #pragma unroll
        for (int o = 16; o > 0; o >>= 1)
            m = fmaxf(m, __shfl_xor_sync(0xffffffffu, m, o));
        float e = (lane < 17) ? expf(scv - m) : 0.f;
        float ssum = e;
        #pragma unroll
        for (int o = 16; o > 0; o >>= 1)
            ssum += __shfl_xor_sync(0xffffffffu, ssum, o);
        float p = e / ssum;

        float a0 = 0.f, a1 = 0.f;
        #pragma unroll
        for (int kk = 0; kk < 17; kk++) {
            float pj = __shfl_sync(0xffffffffu, p, kk);
            a0 += pj * Vs[kk][lane];
            a1 += pj * Vs[kk][lane + 32];
        }
        int t = 1 + qi * NSP + j;
        size_t ob = (size_t)(b * NTOK + t) * DIM + h * 64;
        split_write(a0, g_ahi, g_alo, ob + lane);
        split_write(a1, g_ahi, g_alo, ob + lane + 32);
    }
}

// -------------------- launch -----------------------------------------------
extern "C" void kernel_launch(void* const* d_in, const int* in_sizes, int n_in,
                              void* d_out, int out_size)
{
    const float* x    = (const float*)d_in[0];   // [B, N, 512]
    const float* Wqkv = (const float*)d_in[1];   // [512, 1536]
    const float* Wout = (const float*)d_in[2];   // [512, 512]
    const float* bout = (const float*)d_in[3];   // [512]
    float* out = (float*)d_out;

    // 0) pre-split inputs/weights (globals selected inside kernels)
    xsplit_kernel<<<(MROWS * DIM) / 1024, 256>>>(x);
    {
        dim3 g1(QKVD / 32, DIM / 32);
        wsplit_kernel<<<g1, 256>>>(Wqkv, DIM, QKVD, 0);
        dim3 g2(DIM / 32, DIM / 32);
        wsplit_kernel<<<g2, 256>>>(Wout, DIM, DIM, 1);
    }
    // 1) qkv = x @ Wqkv -> g_qkv
    {
        dim3 grid(QKVD / 128, (MROWS + 127) / 128);
        gemm_mma_kernel<<<grid, 256>>>(nullptr, nullptr, MROWS, QKVD, 0);
    }
    // 2) attention -> g_ahi/g_alo
    cls_partial_kernel<<<512, 256>>>();
    cls_merge_kernel<<<Bb * Hh, 64>>>();
    time_attn_kernel<<<Bb * Hh * NSP, 128>>>();
    // 3) out = attn @ Wout + bias
    {
        dim3 grid(DIM / 128, (MROWS + 127) / 128);
        gemm_mma_kernel<<<grid, 256>>>(bout, out, MROWS, DIM, 1);
    }
}

// round 15
// speedup vs baseline: 2.4413x; 1.1590x over previous
#include <cuda_runtime.h>
#include <cuda_bf16.h>
#include <cstdint>
#include <math.h>

// Problem constants (fixed by setup_inputs)
#define Bb    8
#define Hh    8
#define NSP   196
#define NTOK  3137
#define DIM   512
#define QKVD  1536
#define MROWS 25096        // Bb * NTOK

// -------------------- scratch (__device__ globals, alloc-free) --------------
// RULE (R4-R11): referenced ONLY from device code; never passed as kernel
// arguments from host (host shadow symbol + GB300 ATS = silent host write).
__device__ float         g_qkv [38547456];   // MROWS * QKVD fp32
__device__ __nv_bfloat16 g_xhi [12849152];
__device__ __nv_bfloat16 g_xlo [12849152];
__device__ __nv_bfloat16 g_ahi [12849152];
__device__ __nv_bfloat16 g_alo [12849152];
__device__ __nv_bfloat16 g_wqT_hi[786432];   // Wqkv^T [1536,512]
__device__ __nv_bfloat16 g_wqT_lo[786432];
__device__ __nv_bfloat16 g_woT_hi[262144];   // Wout^T [512,512]
__device__ __nv_bfloat16 g_woT_lo[262144];
__device__ float g_clsm[512];
__device__ float g_clss[512];
__device__ float g_clso[32768];

// -------------------- PTX helpers (sm_80-baseline only) ---------------------
__device__ __forceinline__ uint32_t smem_u32(const void* p) {
    uint32_t a;
    asm("{ .reg .u64 t; cvta.to.shared.u64 t, %1; cvt.u32.u64 %0, t; }"
        : "=r"(a) : "l"(p));
    return a;
}
__device__ __forceinline__ void cp_async16(uint32_t s, const void* g) {
    asm volatile("cp.async.cg.shared.global [%0], [%1], 16;"
                 :: "r"(s), "l"(g) : "memory");
}
#define CP_COMMIT() asm volatile("cp.async.commit_group;" ::: "memory")
#define CP_WAIT0()  asm volatile("cp.async.wait_group 0;" ::: "memory")

__device__ __forceinline__ void ldmx4(uint32_t* r, uint32_t addr) {
    asm volatile("ldmatrix.sync.aligned.m8n8.x4.shared.b16 {%0,%1,%2,%3}, [%4];"
                 : "=r"(r[0]), "=r"(r[1]), "=r"(r[2]), "=r"(r[3]) : "r"(addr));
}
__device__ __forceinline__ void mma_bf16(float* c, const uint32_t* a,
                                         uint32_t b0, uint32_t b1) {
    asm volatile(
        "mma.sync.aligned.m16n8k16.row.col.f32.bf16.bf16.f32 "
        "{%0,%1,%2,%3}, {%4,%5,%6,%7}, {%8,%9}, {%0,%1,%2,%3};"
        : "+f"(c[0]), "+f"(c[1]), "+f"(c[2]), "+f"(c[3])
        : "r"(a[0]), "r"(a[1]), "r"(a[2]), "r"(a[3]), "r"(b0), "r"(b1));
}
__device__ __forceinline__ void split_write(float v, __nv_bfloat16* hi,
                                            __nv_bfloat16* lo, size_t i) {
    __nv_bfloat16 h = __float2bfloat16(v);
    hi[i] = h;
    lo[i] = __float2bfloat16(v - __bfloat162float(h));
}

// -------------------- split x into hi/lo bf16 -------------------------------
__global__ __launch_bounds__(256)
void xsplit_kernel(const float* __restrict__ x) {
    size_t i = ((size_t)blockIdx.x * 256 + threadIdx.x) * 4;
    float4 v = *reinterpret_cast<const float4*>(x + i);
    split_write(v.x, g_xhi, g_xlo, i + 0);
    split_write(v.y, g_xhi, g_xlo, i + 1);
    split_write(v.z, g_xhi, g_xlo, i + 2);
    split_write(v.w, g_xhi, g_xlo, i + 3);
}

// ------------- transpose+split weights: W[K,N] -> T[N,K] (mode-selected) ----
__global__ __launch_bounds__(256)
void wsplit_kernel(const float* __restrict__ W, int K, int N, int mode) {
    __nv_bfloat16* Thi = (mode == 0) ? g_wqT_hi : g_woT_hi;
    __nv_bfloat16* Tlo = (mode == 0) ? g_wqT_lo : g_woT_lo;
    __shared__ float t[32][33];
    int n0 = blockIdx.x * 32, k0 = blockIdx.y * 32;
    int tx = threadIdx.x & 31, ty = threadIdx.x >> 5;   // 32 x 8
    #pragma unroll
    for (int i = 0; i < 4; i++) {
        int k = k0 + ty + i * 8;
        t[ty + i * 8][tx] = W[(size_t)k * N + n0 + tx];
    }
    __syncthreads();
    #pragma unroll
    for (int i = 0; i < 4; i++) {
        int n = n0 + ty + i * 8;
        float v = t[tx][ty + i * 8];
        split_write(v, Thi, Tlo, (size_t)n * K + k0 + tx);
    }
}

// -------------------- mma.sync GEMM (cp.async + 2 CTA/SM) -------------------
// C[M,Nc] = (Ahi+Alo) @ (Bhi+Blo)^T (+bias). 3-term mma, fp32 accum.
// 128x128 tile, k-step 16, double-buffered static smem = 40960 B.
// Row layout (80B pitch): [16 bf16 hi | 16 bf16 lo | 16B pad]; ldmatrix
// phases over 8 rows @80B cover all 32 banks -> conflict-free.
// cp.async.cg staging (no LDG->reg->STS): removes ~256 L1 wavefronts/iter.
#define ROWB   80
#define B_OFF  10240              // 128 rows * 80B
#define STAGEB 20480              // A + B

__global__ __launch_bounds__(256, 2)
void gemm_mma_kernel(const float* __restrict__ bias, float* __restrict__ Cext,
                     int M, int Nc, int mode)
{
    const __nv_bfloat16 *Ahi, *Alo, *Bh, *Bl;
    float* C;
    if (mode == 0) {
        Ahi = g_xhi; Alo = g_xlo; Bh = g_wqT_hi; Bl = g_wqT_lo;
        C = g_qkv;
    } else {
        Ahi = g_ahi; Alo = g_alo; Bh = g_woT_hi; Bl = g_woT_lo;
        C = Cext;
    }

    __shared__ uint32_t smem[2 * STAGEB / 4];   // 40960 B static
    uint32_t sb = smem_u32(smem);

    const int tid = threadIdx.x, wid = tid >> 5, lane = tid & 31;
    const int warpM = wid >> 2, warpN = wid & 3;
    const int gq = lane >> 2, tq = lane & 3;
    const int rowBase = blockIdx.y * 128, colBase = blockIdx.x * 128;

    // staging: thread -> (row = tid>>1, k-half = tid&1), 8 bf16 = 16B each
    const int srow = tid >> 1, skh = tid & 1;
    const int agr = min(rowBase + srow, M - 1);
    const size_t aoffg = (size_t)agr * DIM + skh * 8;
    const size_t boffg = (size_t)(colBase + srow) * DIM + skh * 8;
    const uint32_t soff = (uint32_t)srow * ROWB + (uint32_t)skh * 16;

    // ldmatrix lane addressing
    const int arow  = lane & 15;
    const uint32_t aksel = (uint32_t)(lane >> 4) * 16;
    const int brow  = lane & 7;
    const uint32_t bksel = (uint32_t)((lane >> 3) & 1) * 16;
    const int bnsel = lane >> 4;

    float acc[4][4][4];
    #pragma unroll
    for (int i = 0; i < 4; i++)
        #pragma unroll
        for (int j = 0; j < 4; j++)
            #pragma unroll
            for (int e = 0; e < 4; e++) acc[i][j][e] = 0.f;

    // prologue: stage 0 via cp.async
    cp_async16(sb + soff,              Ahi + aoffg);
    cp_async16(sb + soff + 32,         Alo + aoffg);
    cp_async16(sb + soff + B_OFF,      Bh + boffg);
    cp_async16(sb + soff + B_OFF + 32, Bl + boffg);
    CP_COMMIT();

    const int nIter = DIM / 16;   // 32
    for (int it = 0; it < nIter; it++) {
        CP_WAIT0();               // this thread's copies into buf(it&1) done
        __syncthreads();          // all threads' copies visible; prior reads done

        uint32_t stg = sb + (uint32_t)(it & 1) * STAGEB;
        uint32_t abase = stg + (uint32_t)(warpM * 64 + arow) * ROWB + aksel;
        uint32_t bbase = stg + B_OFF
                       + (uint32_t)(warpN * 32 + bnsel * 8 + brow) * ROWB
                       + bksel;

        // B fragments (kept across both passes)
        uint32_t bhf[2][4], blf[2][4];
        #pragma unroll
        for (int p = 0; p < 2; p++) {
            ldmx4(bhf[p], bbase + (uint32_t)p * (16 * ROWB));
            ldmx4(blf[p], bbase + (uint32_t)p * (16 * ROWB) + 32);
        }
        // A-hi fragments
        uint32_t af[4][4];
        #pragma unroll
        for (int mf = 0; mf < 4; mf++)
            ldmx4(af[mf], abase + (uint32_t)mf * (16 * ROWB));

        // issue next stage copy (overlaps the MMA burst below)
        if (it + 1 < nIter) {
            uint32_t st = sb + (uint32_t)((it + 1) & 1) * STAGEB;
            int k0 = (it + 1) * 16;
            cp_async16(st + soff,              Ahi + aoffg + k0);
            cp_async16(st + soff + 32,         Alo + aoffg + k0);
            cp_async16(st + soff + B_OFF,      Bh + boffg + k0);
            cp_async16(st + soff + B_OFF + 32, Bl + boffg + k0);
        }
        CP_COMMIT();

        // pass 1: Ahi*Bhi + Ahi*Blo
        #pragma unroll
        for (int mf = 0; mf < 4; mf++)
            #pragma unroll
            for (int nf = 0; nf < 4; nf++) {
                int p = nf >> 1, q = nf & 1;
                mma_bf16(acc[mf][nf], af[mf], bhf[p][q*2], bhf[p][q*2+1]);
                mma_bf16(acc[mf][nf], af[mf], blf[p][q*2], blf[p][q*2+1]);
            }
        // pass 2: A-lo fragments (reuse regs), Alo*Bhi
        #pragma unroll
        for (int mf = 0; mf < 4; mf++)
            ldmx4(af[mf], abase + (uint32_t)mf * (16 * ROWB) + 32);
        #pragma unroll
        for (int mf = 0; mf < 4; mf++)
            #pragma unroll
            for (int nf = 0; nf < 4; nf++) {
                int p = nf >> 1, q = nf & 1;
                mma_bf16(acc[mf][nf], af[mf], bhf[p][q*2], bhf[p][q*2+1]);
            }
    }

    // epilogue: direct float2 stores (documented C fragment layout)
    #pragma unroll
    for (int nf = 0; nf < 4; nf++) {
        int col = colBase + warpN * 32 + nf * 8 + tq * 2;
        float2 bv = make_float2(0.f, 0.f);
        if (bias) bv = *reinterpret_cast<const float2*>(&bias[col]);
        #pragma unroll
        for (int mf = 0; mf < 4; mf++) {
            int r0 = rowBase + warpM * 64 + mf * 16 + gq;
            if (r0 < M) {
                float2 v = make_float2(acc[mf][nf][0] + bv.x,
                                       acc[mf][nf][1] + bv.y);
                *reinterpret_cast<float2*>(&C[(size_t)r0 * Nc + col]) = v;
            }
            int r1 = r0 + 8;
            if (r1 < M) {
                float2 v = make_float2(acc[mf][nf][2] + bv.x,
                                       acc[mf][nf][3] + bv.y);
                *reinterpret_cast<float2*>(&C[(size_t)r1 * Nc + col]) = v;
            }
        }
    }
}

// -------------------- CLS attention: chunked partials + merge ---------------
#define CLS_CH 393     // ceil(3137/8)

__global__ __launch_bounds__(256)
void cls_partial_kernel()
{
    __shared__ float sq[64];
    __shared__ float sc[CLS_CH];
    __shared__ float red[256];

    const int bx = blockIdx.x;           // bh*8 + c
    const int bh = bx >> 3, c = bx & 7;
    const int b = bh / Hh, h = bh % Hh;
    const int tid = threadIdx.x;
    const float scale = 0.125f;
    const int t0 = c * CLS_CH, t1 = min(NTOK, t0 + CLS_CH);

    if (tid < 64)
        sq[tid] = g_qkv[(size_t)(b * NTOK) * QKVD + h * 64 + tid] * scale;
    __syncthreads();

    float lmax = -1e30f;
    for (int t = t0 + tid; t < t1; t += 256) {
        const float4* kp = reinterpret_cast<const float4*>(
            &g_qkv[(size_t)(b * NTOK + t) * QKVD + DIM + h * 64]);
        float d0 = 0.f, d1 = 0.f, d2 = 0.f, d3 = 0.f;
        #pragma unroll
        for (int i = 0; i < 16; i++) {
            float4 kv = kp[i];
            d0 += sq[4*i+0] * kv.x; d1 += sq[4*i+1] * kv.y;
            d2 += sq[4*i+2] * kv.z; d3 += sq[4*i+3] * kv.w;
        }
        float dot = (d0 + d1) + (d2 + d3);
        sc[t - t0] = dot;
        lmax = fmaxf(lmax, dot);
    }
    red[tid] = lmax; __syncthreads();
    for (int s = 128; s > 0; s >>= 1) {
        if (tid < s) red[tid] = fmaxf(red[tid], red[tid + s]);
        __syncthreads();
    }
    const float m = red[0];
    __syncthreads();

    float lsum = 0.f;
    for (int t = t0 + tid; t < t1; t += 256) {
        float e = expf(sc[t - t0] - m);
        sc[t - t0] = e;
        lsum += e;
    }
    red[tid] = lsum; __syncthreads();
    for (int s = 128; s > 0; s >>= 1) {
        if (tid < s) red[tid] += red[tid + s];
        __syncthreads();
    }
    const float ssum = red[0];
    __syncthreads();

    const int d = tid & 63, chunk = tid >> 6;
    float acc = 0.f;
    for (int t = t0 + chunk; t < t1; t += 4)
        acc += sc[t - t0] * g_qkv[(size_t)(b * NTOK + t) * QKVD + 2 * DIM + h * 64 + d];
    red[tid] = acc; __syncthreads();
    if (chunk == 0) {
        float tot = acc + red[tid + 64] + red[tid + 128] + red[tid + 192];
        g_clso[bx * 64 + d] = tot;
        if (d == 0) { g_clsm[bx] = m; g_clss[bx] = ssum; }
    }
}

__global__ __launch_bounds__(64)
void cls_merge_kernel()
{
    const int bh = blockIdx.x;
    const int b = bh / Hh, h = bh % Hh;
    const int d = threadIdx.x;

    float M = -1e30f;
    #pragma unroll
    for (int c = 0; c < 8; c++) M = fmaxf(M, g_clsm[bh * 8 + c]);
    float S = 0.f, O = 0.f;
    #pragma unroll
    for (int c = 0; c < 8; c++) {
        float w = expf(g_clsm[bh * 8 + c] - M);
        S += g_clss[bh * 8 + c] * w;
        O += g_clso[(bh * 8 + c) * 64 + d] * w;
    }
    split_write(O / S, g_ahi, g_alo, (size_t)(b * NTOK) * DIM + h * 64 + d);
}

// -------------------- time attention (float4 + 2q per pass) -----------------
__global__ __launch_bounds__(128)
void time_attn_kernel()
{
    // pitch 68 floats: float4-aligned rows; float4 LDS bank-walk conflict-free
    __shared__ __align__(16) float Qs[16][68];
    __shared__ __align__(16) float Ks[17][68];
    __shared__ __align__(16) float Vs[17][68];

    const int s  = blockIdx.x;
    const int bh = s / NSP, j = s % NSP;
    const int b  = bh / Hh, h = bh % Hh;
    const int tid = threadIdx.x;
    const float scale = 0.125f;

    for (int idx = tid; idx < 16 * 16; idx += 128) {
        int i = idx >> 4, d4 = (idx & 15) * 4;
        int t = 1 + i * NSP + j;
        float4 q = *reinterpret_cast<const float4*>(
            &g_qkv[(size_t)(b * NTOK + t) * QKVD + h * 64 + d4]);
        q.x *= scale; q.y *= scale; q.z *= scale; q.w *= scale;
        *reinterpret_cast<float4*>(&Qs[i][d4]) = q;
    }
    for (int idx = tid; idx < 17 * 16; idx += 128) {
        int key = idx >> 4, d4 = (idx & 15) * 4;
        int t = (key == 0) ? 0 : 1 + (key - 1) * NSP + j;
        size_t base = (size_t)(b * NTOK + t) * QKVD + h * 64 + d4;
        *reinterpret_cast<float4*>(&Ks[key][d4]) =
            *reinterpret_cast<const float4*>(&g_qkv[base + DIM]);
        *reinterpret_cast<float4*>(&Vs[key][d4]) =
            *reinterpret_cast<const float4*>(&g_qkv[base + 2 * DIM]);
    }
    __syncthreads();

    const int w = tid >> 5, lane = tid & 31;
    #pragma unroll
    for (int pass = 0; pass < 2; pass++) {
        const int q0 = w * 2 + pass * 8, q1 = q0 + 1;
        float s0 = -1e30f, s1 = -1e30f;
        if (lane < 17) {
            float a0 = 0.f, a1 = 0.f;
            #pragma unroll
            for (int dd = 0; dd < 16; dd++) {
                float4 kv = *reinterpret_cast<const float4*>(&Ks[lane][dd * 4]);
                float4 qa = *reinterpret_cast<const float4*>(&Qs[q0][dd * 4]);
                float4 qb = *reinterpret_cast<const float4*>(&Qs[q1][dd * 4]);
                a0 += qa.x*kv.x + qa.y*kv.y + qa.z*kv.z + qa.w*kv.w;
                a1 += qb.x*kv.x + qb.y*kv.y + qb.z*kv.z + qb.w*kv.w;
            }
            s0 = a0; s1 = a1;
        }
        float m0 = s0, m1 = s1;
        #pragma unroll
        for (int o = 16; o > 0; o >>= 1) {
            m0 = fmaxf(m0, __shfl_xor_sync(0xffffffffu, m0, o));
            m1 = fmaxf(m1, __shfl_xor_sync(0xffffffffu, m1, o));
        }
        float e0 = (lane < 17) ? expf(s0 - m0) : 0.f;
        float e1 = (lane < 17) ? expf(s1 - m1) : 0.f;
        float t0 = e0, t1 = e1;
        #pragma unroll
        for (int o = 16; o > 0; o >>= 1) {
            t0 += __shfl_xor_sync(0xffffffffu, t0, o);
            t1 += __shfl_xor_sync(0xffffffffu, t1, o);
        }
        float p0 = e0 / t0, p1 = e1 / t1;

        float a00 = 0.f, a01 = 0.f, a10 = 0.f, a11 = 0.f;
        #pragma unroll
        for (int kk = 0; kk < 17; kk++) {
            float pj0 = __shfl_sync(0xffffffffu, p0, kk);
            float pj1 = __shfl_sync(0xffffffffu, p1, kk);
            float v0 = Vs[kk][lane], v1 = Vs[kk][lane + 32];
            a00 += pj0 * v0; a01 += pj0 * v1;
            a10 += pj1 * v0; a11 += pj1 * v1;
        }
        {
            int t = 1 + q0 * NSP + j;
            size_t ob = (size_t)(b * NTOK + t) * DIM + h * 64;
            split_write(a00, g_ahi, g_alo, ob + lane);
            split_write(a01, g_ahi, g_alo, ob + lane + 32);
        }
        {
            int t = 1 + q1 * NSP + j;
            size_t ob = (size_t)(b * NTOK + t) * DIM + h * 64;
            split_write(a10, g_ahi, g_alo, ob + lane);
            split_write(a11, g_ahi, g_alo, ob + lane + 32);
        }
    }
}

// -------------------- launch -----------------------------------------------
extern "C" void kernel_launch(void* const* d_in, const int* in_sizes, int n_in,
                              void* d_out, int out_size)
{
    const float* x    = (const float*)d_in[0];   // [B, N, 512]
    const float* Wqkv = (const float*)d_in[1];   // [512, 1536]
    const float* Wout = (const float*)d_in[2];   // [512, 512]
    const float* bout = (const float*)d_in[3];   // [512]
    float* out = (float*)d_out;

    // 0) pre-split inputs/weights (globals selected inside kernels)
    xsplit_kernel<<<(MROWS * DIM) / 1024, 256>>>(x);
    {
        dim3 g1(QKVD / 32, DIM / 32);
        wsplit_kernel<<<g1, 256>>>(Wqkv, DIM, QKVD, 0);
        dim3 g2(DIM / 32, DIM / 32);
        wsplit_kernel<<<g2, 256>>>(Wout, DIM, DIM, 1);
    }
    // 1) qkv = x @ Wqkv -> g_qkv
    {
        dim3 grid(QKVD / 128, (MROWS + 127) / 128);
        gemm_mma_kernel<<<grid, 256>>>(nullptr, nullptr, MROWS, QKVD, 0);
    }
    // 2) attention -> g_ahi/g_alo
    cls_partial_kernel<<<512, 256>>>();
    cls_merge_kernel<<<Bb * Hh, 64>>>();
    time_attn_kernel<<<Bb * Hh * NSP, 128>>>();
    // 3) out = attn @ Wout + bias
    {
        dim3 grid(DIM / 128, (MROWS + 127) / 128);
        gemm_mma_kernel<<<grid, 256>>>(bout, out, MROWS, DIM, 1);
    }
}